// round 2
// baseline (speedup 1.0000x reference)
#include <cuda_runtime.h>
#include <cstdint>

#define NATTRS 250
#define NOBJS  400
#define NNODES 650
#define NEDGES 100000
#define DIN    512
#define DHID   4096
#define DNODE  512
#define FEATD  2048
#define EMBD   800
#define BATCH  256
#define P1D    1200
#define NPAIRS (NATTRS * NOBJS)   /* 100000 */
#define LNEPS  1e-5f

// ---------------- scratch layout (single __device__ global; no allocs) ----------------
#define OFF_ADJ    0ull
#define OFF_MEAN1  (OFF_ADJ   + (size_t)NNODES * NNODES)        // 422500
#define OFF_H      (OFF_MEAN1 + (size_t)NNODES * DIN)
#define OFF_MEAN2  (OFF_H     + (size_t)NNODES * DHID)
#define OFF_ON     (OFF_MEAN2 + (size_t)NNODES * DHID)
#define OFF_PA     (OFF_ON    + (size_t)NNODES * DNODE)
#define OFF_PO     (OFF_PA    + (size_t)NATTRS * P1D)
#define OFF_S      (OFF_PO    + (size_t)NOBJS  * P1D)
#define OFF_Q      (OFF_S     + (size_t)NPAIRS * P1D)
#define OFF_I1     (OFF_Q     + (size_t)NPAIRS * EMBD)
#define OFF_I2     (OFF_I1    + (size_t)BATCH * 768)
#define OFF_I3     (OFF_I2    + (size_t)BATCH * 1000)
#define SCRATCH_ELEMS (OFF_I3 + (size_t)BATCH * EMBD)

__device__ float g_scratch[SCRATCH_ELEMS];

// ---------------- small kernels ----------------
__global__ void zero_kernel(float* p, int n) {
    int i = blockIdx.x * blockDim.x + threadIdx.x;
    if (i < n) p[i] = 0.0f;
}

__global__ void edge_count_kernel(const int* __restrict__ src,
                                  const int* __restrict__ dst,
                                  float* __restrict__ adj) {
    int e = blockIdx.x * blockDim.x + threadIdx.x;
    if (e < NEDGES) {
        atomicAdd(&adj[(size_t)dst[e] * NNODES + src[e]], 1.0f);
    }
}

// row-normalize adjacency: adj[r, :] /= max(rowsum, 1)
__global__ void row_norm_kernel(float* __restrict__ adj) {
    __shared__ float sbuf[32];
    int r = blockIdx.x;
    int tid = threadIdx.x;
    float s = 0.0f;
    float* row = adj + (size_t)r * NNODES;
    for (int c = tid; c < NNODES; c += blockDim.x) s += row[c];
    for (int o = 16; o > 0; o >>= 1) s += __shfl_down_sync(0xffffffffu, s, o);
    if ((tid & 31) == 0) sbuf[tid >> 5] = s;
    __syncthreads();
    int nw = blockDim.x >> 5;
    if (tid < 32) {
        s = (tid < nw) ? sbuf[tid] : 0.0f;
        for (int o = 16; o > 0; o >>= 1) s += __shfl_down_sync(0xffffffffu, s, o);
        if (tid == 0) sbuf[0] = s;
    }
    __syncthreads();
    float inv = 1.0f / fmaxf(sbuf[0], 1.0f);
    for (int c = tid; c < NNODES; c += blockDim.x) row[c] *= inv;
}

// S[r,k] = relu(PA[r/NOBJS,k] + PO[r%NOBJS,k])   (bp1 folded into PA)
__global__ void pair_relu_kernel(const float* __restrict__ PA,
                                 const float* __restrict__ PO,
                                 float* __restrict__ S) {
    int r = blockIdx.x;
    const float* pa = PA + (size_t)(r / NOBJS) * P1D;
    const float* po = PO + (size_t)(r % NOBJS) * P1D;
    float* s = S + (size_t)r * P1D;
    for (int k = threadIdx.x; k < P1D; k += blockDim.x)
        s[k] = fmaxf(pa[k] + po[k], 0.0f);
}

// in-place LayerNorm over last dim D, with gain g and bias b
__global__ void ln_kernel(float* __restrict__ X,
                          const float* __restrict__ g,
                          const float* __restrict__ b,
                          int D) {
    __shared__ float sA[32], sB[32];
    int r = blockIdx.x;
    int tid = threadIdx.x;
    float* x = X + (size_t)r * D;
    float s = 0.0f, s2 = 0.0f;
    for (int d = tid; d < D; d += blockDim.x) {
        float v = x[d];
        s += v; s2 += v * v;
    }
    for (int o = 16; o > 0; o >>= 1) {
        s  += __shfl_down_sync(0xffffffffu, s,  o);
        s2 += __shfl_down_sync(0xffffffffu, s2, o);
    }
    if ((tid & 31) == 0) { sA[tid >> 5] = s; sB[tid >> 5] = s2; }
    __syncthreads();
    int nw = blockDim.x >> 5;
    if (tid < 32) {
        s  = (tid < nw) ? sA[tid] : 0.0f;
        s2 = (tid < nw) ? sB[tid] : 0.0f;
        for (int o = 16; o > 0; o >>= 1) {
            s  += __shfl_down_sync(0xffffffffu, s,  o);
            s2 += __shfl_down_sync(0xffffffffu, s2, o);
        }
        if (tid == 0) { sA[0] = s; sB[0] = s2; }
    }
    __syncthreads();
    float invD = 1.0f / (float)D;
    float m = sA[0] * invD;
    float var = fmaxf(sB[0] * invD - m * m, 0.0f);
    float inv = rsqrtf(var + LNEPS);
    for (int d = tid; d < D; d += blockDim.x) {
        float v = x[d];
        x[d] = (v - m) * inv * g[d] + b[d];
    }
}

// ---------------- tiled GEMMs (128x128x8, 256 threads, 8x8 microtile) ----------------
// C[M,N] = A[M,K] @ B^T   (B is [N,K] row-major, leading dim ldb)
__global__ __launch_bounds__(256)
void gemm_nt_kernel(const float* __restrict__ A, int lda,
                    const float* __restrict__ B, int ldb,
                    float* __restrict__ C, int ldc,
                    int M, int N, int K,
                    const float* __restrict__ bias,
                    int accumulate, int do_relu) {
    __shared__ float As[8][128];
    __shared__ float Bs[8][128];
    int tid = threadIdx.x;
    int bm = blockIdx.y * 128;
    int bn = blockIdx.x * 128;
    int ty = tid >> 4;     // 0..15
    int tx = tid & 15;     // 0..15
    float acc[8][8];
#pragma unroll
    for (int i = 0; i < 8; i++)
#pragma unroll
        for (int j = 0; j < 8; j++) acc[i][j] = 0.0f;

    for (int k0 = 0; k0 < K; k0 += 8) {
#pragma unroll
        for (int l = 0; l < 4; l++) {
            int e = tid + l * 256;
            int m = e & 127;
            int kk = e >> 7;
            int gk = k0 + kk;
            int gm = bm + m;
            As[kk][m] = (gm < M && gk < K) ? A[(size_t)gm * lda + gk] : 0.0f;
            int gn = bn + m;
            Bs[kk][m] = (gn < N && gk < K) ? B[(size_t)gn * ldb + gk] : 0.0f;
        }
        __syncthreads();
#pragma unroll
        for (int kk = 0; kk < 8; kk++) {
            float a[8], b[8];
#pragma unroll
            for (int i = 0; i < 8; i++) a[i] = As[kk][ty * 8 + i];
#pragma unroll
            for (int j = 0; j < 8; j++) b[j] = Bs[kk][tx * 8 + j];
#pragma unroll
            for (int i = 0; i < 8; i++)
#pragma unroll
                for (int j = 0; j < 8; j++) acc[i][j] += a[i] * b[j];
        }
        __syncthreads();
    }

#pragma unroll
    for (int i = 0; i < 8; i++) {
        int m = bm + ty * 8 + i;
        if (m >= M) continue;
#pragma unroll
        for (int j = 0; j < 8; j++) {
            int n = bn + tx * 8 + j;
            if (n >= N) continue;
            float v = acc[i][j];
            if (bias) v += bias[n];
            if (accumulate) v += C[(size_t)m * ldc + n];
            if (do_relu) v = fmaxf(v, 0.0f);
            C[(size_t)m * ldc + n] = v;
        }
    }
}

// C[M,N] = A[M,K] @ B[K,N]   (B row-major, leading dim ldb)
__global__ __launch_bounds__(256)
void gemm_nn_kernel(const float* __restrict__ A, int lda,
                    const float* __restrict__ B, int ldb,
                    float* __restrict__ C, int ldc,
                    int M, int N, int K) {
    __shared__ float As[8][128];
    __shared__ float Bs[8][128];
    int tid = threadIdx.x;
    int bm = blockIdx.y * 128;
    int bn = blockIdx.x * 128;
    int ty = tid >> 4;
    int tx = tid & 15;
    float acc[8][8];
#pragma unroll
    for (int i = 0; i < 8; i++)
#pragma unroll
        for (int j = 0; j < 8; j++) acc[i][j] = 0.0f;

    for (int k0 = 0; k0 < K; k0 += 8) {
#pragma unroll
        for (int l = 0; l < 4; l++) {
            int e = tid + l * 256;
            int m = e & 127;
            int kk = e >> 7;
            int gk = k0 + kk;
            int gm = bm + m;
            As[kk][m] = (gm < M && gk < K) ? A[(size_t)gm * lda + gk] : 0.0f;
            int gn = bn + m;
            Bs[kk][m] = (gn < N && gk < K) ? B[(size_t)gk * ldb + gn] : 0.0f;
        }
        __syncthreads();
#pragma unroll
        for (int kk = 0; kk < 8; kk++) {
            float a[8], b[8];
#pragma unroll
            for (int i = 0; i < 8; i++) a[i] = As[kk][ty * 8 + i];
#pragma unroll
            for (int j = 0; j < 8; j++) b[j] = Bs[kk][tx * 8 + j];
#pragma unroll
            for (int i = 0; i < 8; i++)
#pragma unroll
                for (int j = 0; j < 8; j++) acc[i][j] += a[i] * b[j];
        }
        __syncthreads();
    }
#pragma unroll
    for (int i = 0; i < 8; i++) {
        int m = bm + ty * 8 + i;
        if (m >= M) continue;
#pragma unroll
        for (int j = 0; j < 8; j++) {
            int n = bn + tx * 8 + j;
            if (n >= N) continue;
            C[(size_t)m * ldc + n] = acc[i][j];
        }
    }
}

// ---------------- host-side helpers ----------------
static inline dim3 gemm_grid(int M, int N) {
    return dim3((N + 127) / 128, (M + 127) / 128);
}

extern "C" void kernel_launch(void* const* d_in, const int* in_sizes, int n_in,
                              void* d_out, int out_size) {
    const float* img   = (const float*)d_in[0];
    const float* nodes = (const float*)d_in[1];
    const int*   esrc  = (const int*)d_in[2];
    const int*   edst  = (const int*)d_in[3];
    const float* W1l   = (const float*)d_in[4];
    const float* b1    = (const float*)d_in[5];
    const float* W1r   = (const float*)d_in[6];
    const float* W2l   = (const float*)d_in[7];
    const float* b2    = (const float*)d_in[8];
    const float* W2r   = (const float*)d_in[9];
    const float* Wp1   = (const float*)d_in[10];
    const float* bp1   = (const float*)d_in[11];
    const float* Wp2   = (const float*)d_in[12];
    const float* bp2   = (const float*)d_in[13];
    const float* gp    = (const float*)d_in[14];
    const float* bpn   = (const float*)d_in[15];
    const float* Wi1   = (const float*)d_in[16];
    const float* bi1   = (const float*)d_in[17];
    const float* Wi2   = (const float*)d_in[18];
    const float* bi2   = (const float*)d_in[19];
    const float* Wi3   = (const float*)d_in[20];
    const float* bi3   = (const float*)d_in[21];
    const float* gi    = (const float*)d_in[22];
    const float* bin_  = (const float*)d_in[23];
    float* out = (float*)d_out;

    void* sp = nullptr;
    cudaGetSymbolAddress(&sp, g_scratch);
    float* S0 = (float*)sp;

    float* adj   = S0 + OFF_ADJ;
    float* mean1 = S0 + OFF_MEAN1;
    float* h     = S0 + OFF_H;
    float* mean2 = S0 + OFF_MEAN2;
    float* on    = S0 + OFF_ON;
    float* PA    = S0 + OFF_PA;
    float* PO    = S0 + OFF_PO;
    float* S     = S0 + OFF_S;
    float* Q     = S0 + OFF_Q;
    float* i1    = S0 + OFF_I1;
    float* i2    = S0 + OFF_I2;
    float* i3    = S0 + OFF_I3;

    // ---- graph: dense normalized adjacency ----
    {
        int n = NNODES * NNODES;
        zero_kernel<<<(n + 255) / 256, 256>>>(adj, n);
        edge_count_kernel<<<(NEDGES + 255) / 256, 256>>>(esrc, edst, adj);
        row_norm_kernel<<<NNODES, 256>>>(adj);
    }

    // ---- SAGE layer 1: h = relu(Âx @ W1l^T + b1 + x @ W1r^T) ----
    gemm_nn_kernel<<<gemm_grid(NNODES, DIN), 256>>>(adj, NNODES, nodes, DIN,
                                                    mean1, DIN, NNODES, DIN, NNODES);
    gemm_nt_kernel<<<gemm_grid(NNODES, DHID), 256>>>(mean1, DIN, W1l, DIN,
                                                     h, DHID, NNODES, DHID, DIN,
                                                     b1, 0, 0);
    gemm_nt_kernel<<<gemm_grid(NNODES, DHID), 256>>>(nodes, DIN, W1r, DIN,
                                                     h, DHID, NNODES, DHID, DIN,
                                                     nullptr, 1, 1);

    // ---- SAGE layer 2: on = Âh @ W2l^T + b2 + h @ W2r^T ----
    gemm_nn_kernel<<<gemm_grid(NNODES, DHID), 256>>>(adj, NNODES, h, DHID,
                                                     mean2, DHID, NNODES, DHID, NNODES);
    gemm_nt_kernel<<<gemm_grid(NNODES, DNODE), 256>>>(mean2, DHID, W2l, DHID,
                                                      on, DNODE, NNODES, DNODE, DHID,
                                                      b2, 0, 0);
    gemm_nt_kernel<<<gemm_grid(NNODES, DNODE), 256>>>(h, DHID, W2r, DHID,
                                                      on, DNODE, NNODES, DNODE, DHID,
                                                      nullptr, 1, 0);

    // ---- pairs MLP, factored: PA = attr@Wp1[:,:512]^T + bp1 ; PO = obj@Wp1[:,512:]^T ----
    const float* attr = on;                       // rows [0, 250)
    const float* obj  = on + (size_t)NATTRS * DNODE;  // rows [250, 650)
    gemm_nt_kernel<<<gemm_grid(NATTRS, P1D), 256>>>(attr, DNODE, Wp1, 2 * DNODE,
                                                    PA, P1D, NATTRS, P1D, DNODE,
                                                    bp1, 0, 0);
    gemm_nt_kernel<<<gemm_grid(NOBJS, P1D), 256>>>(obj, DNODE, Wp1 + DNODE, 2 * DNODE,
                                                   PO, P1D, NOBJS, P1D, DNODE,
                                                   nullptr, 0, 0);

    // S[r,:] = relu(PA[i] + PO[j])
    pair_relu_kernel<<<NPAIRS, 256>>>(PA, PO, S);

    // Q = S @ Wp2^T + bp2 ; then LN in place -> P
    gemm_nt_kernel<<<gemm_grid(NPAIRS, EMBD), 256>>>(S, P1D, Wp2, P1D,
                                                     Q, EMBD, NPAIRS, EMBD, P1D,
                                                     bp2, 0, 0);
    ln_kernel<<<NPAIRS, 256>>>(Q, gp, bpn, EMBD);

    // ---- image MLP ----
    gemm_nt_kernel<<<gemm_grid(BATCH, 768), 256>>>(img, FEATD, Wi1, FEATD,
                                                   i1, 768, BATCH, 768, FEATD,
                                                   bi1, 0, 1);
    gemm_nt_kernel<<<gemm_grid(BATCH, 1000), 256>>>(i1, 768, Wi2, 768,
                                                    i2, 1000, BATCH, 1000, 768,
                                                    bi2, 0, 1);
    gemm_nt_kernel<<<gemm_grid(BATCH, EMBD), 256>>>(i2, 1000, Wi3, 1000,
                                                    i3, EMBD, BATCH, EMBD, 1000,
                                                    bi3, 0, 0);
    ln_kernel<<<BATCH, 256>>>(i3, gi, bin_, EMBD);

    // ---- out = iLN @ P^T  [256, 100000] ----
    gemm_nt_kernel<<<gemm_grid(BATCH, NPAIRS), 256>>>(i3, EMBD, Q, EMBD,
                                                      out, NPAIRS, BATCH, NPAIRS, EMBD,
                                                      nullptr, 0, 0);
}

// round 3
// speedup vs baseline: 1.8964x; 1.8964x over previous
#include <cuda_runtime.h>
#include <cuda_bf16.h>
#include <cstdint>

#define NATTRS 250
#define NOBJS  400
#define NNODES 650
#define NEDGES 100000
#define DIN    512
#define DHID   4096
#define DNODE  512
#define FEATD  2048
#define EMBD   800
#define BATCH  256
#define P1D    1200
#define NPAIRS (NATTRS * NOBJS)   /* 100000 */
#define LNEPS  1e-5f

// ---------------- scratch layout (single __device__ global; no allocs) ----------------
#define OFF_ADJ    0ull
#define OFF_MEAN1  (OFF_ADJ   + (size_t)NNODES * NNODES)
#define OFF_H      (OFF_MEAN1 + (size_t)NNODES * DIN)
#define OFF_MEAN2  (OFF_H     + (size_t)NNODES * DHID)
#define OFF_ON     (OFF_MEAN2 + (size_t)NNODES * DHID)
#define OFF_PA     (OFF_ON    + (size_t)NNODES * DNODE)
#define OFF_PO     (OFF_PA    + (size_t)NATTRS * P1D)
#define OFF_Q      (OFF_PO    + (size_t)NOBJS  * P1D)
#define OFF_I1     (OFF_Q     + (size_t)NPAIRS * EMBD)
#define OFF_I2     (OFF_I1    + (size_t)BATCH * 768)
#define OFF_I3     (OFF_I2    + (size_t)BATCH * 1000)
#define SCRATCH_ELEMS (OFF_I3 + (size_t)BATCH * EMBD)

__device__ float g_scratch[SCRATCH_ELEMS];
__device__ __nv_bfloat16 g_wp2hi[(size_t)EMBD * P1D];
__device__ __nv_bfloat16 g_wp2lo[(size_t)EMBD * P1D];
__device__ __nv_bfloat16 g_phi[(size_t)NPAIRS * EMBD];
__device__ __nv_bfloat16 g_plo[(size_t)NPAIRS * EMBD];

// ---------------- small kernels ----------------
__global__ void zero_kernel(float* p, int n) {
    int i = blockIdx.x * blockDim.x + threadIdx.x;
    if (i < n) p[i] = 0.0f;
}

__global__ void edge_count_kernel(const int* __restrict__ src,
                                  const int* __restrict__ dst,
                                  float* __restrict__ adj) {
    int e = blockIdx.x * blockDim.x + threadIdx.x;
    if (e < NEDGES) atomicAdd(&adj[(size_t)dst[e] * NNODES + src[e]], 1.0f);
}

__global__ void row_norm_kernel(float* __restrict__ adj) {
    __shared__ float sbuf[32];
    int r = blockIdx.x;
    int tid = threadIdx.x;
    float s = 0.0f;
    float* row = adj + (size_t)r * NNODES;
    for (int c = tid; c < NNODES; c += blockDim.x) s += row[c];
    for (int o = 16; o > 0; o >>= 1) s += __shfl_down_sync(0xffffffffu, s, o);
    if ((tid & 31) == 0) sbuf[tid >> 5] = s;
    __syncthreads();
    int nw = blockDim.x >> 5;
    if (tid < 32) {
        s = (tid < nw) ? sbuf[tid] : 0.0f;
        for (int o = 16; o > 0; o >>= 1) s += __shfl_down_sync(0xffffffffu, s, o);
        if (tid == 0) sbuf[0] = s;
    }
    __syncthreads();
    float inv = 1.0f / fmaxf(sbuf[0], 1.0f);
    for (int c = tid; c < NNODES; c += blockDim.x) row[c] *= inv;
}

// split fp32 -> (hi, lo) bf16
__global__ void split_kernel(const float* __restrict__ x,
                             __nv_bfloat16* __restrict__ hi,
                             __nv_bfloat16* __restrict__ lo, int n) {
    int i = blockIdx.x * blockDim.x + threadIdx.x;
    if (i < n) {
        float v = x[i];
        __nv_bfloat16 h = __float2bfloat16(v);
        hi[i] = h;
        lo[i] = __float2bfloat16(v - __bfloat162float(h));
    }
}

// in-place LayerNorm (fp32)
__global__ void ln_kernel(float* __restrict__ X,
                          const float* __restrict__ g,
                          const float* __restrict__ b, int D) {
    __shared__ float sA[32], sB[32];
    int r = blockIdx.x;
    int tid = threadIdx.x;
    float* x = X + (size_t)r * D;
    float s = 0.0f, s2 = 0.0f;
    for (int d = tid; d < D; d += blockDim.x) { float v = x[d]; s += v; s2 += v * v; }
    for (int o = 16; o > 0; o >>= 1) {
        s += __shfl_down_sync(0xffffffffu, s, o);
        s2 += __shfl_down_sync(0xffffffffu, s2, o);
    }
    if ((tid & 31) == 0) { sA[tid >> 5] = s; sB[tid >> 5] = s2; }
    __syncthreads();
    int nw = blockDim.x >> 5;
    if (tid < 32) {
        s = (tid < nw) ? sA[tid] : 0.0f;
        s2 = (tid < nw) ? sB[tid] : 0.0f;
        for (int o = 16; o > 0; o >>= 1) {
            s += __shfl_down_sync(0xffffffffu, s, o);
            s2 += __shfl_down_sync(0xffffffffu, s2, o);
        }
        if (tid == 0) { sA[0] = s; sB[0] = s2; }
    }
    __syncthreads();
    float invD = 1.0f / (float)D;
    float m = sA[0] * invD;
    float var = fmaxf(sB[0] * invD - m * m, 0.0f);
    float inv = rsqrtf(var + LNEPS);
    for (int d = tid; d < D; d += blockDim.x)
        x[d] = (x[d] - m) * inv * g[d] + b[d];
}

// LayerNorm of Q rows -> write split bf16 P (hi/lo)
__global__ void ln_split_kernel(const float* __restrict__ Q,
                                const float* __restrict__ g,
                                const float* __restrict__ b,
                                __nv_bfloat16* __restrict__ Phi,
                                __nv_bfloat16* __restrict__ Plo) {
    __shared__ float sA[32], sB[32];
    int r = blockIdx.x;
    int tid = threadIdx.x;
    const float* x = Q + (size_t)r * EMBD;
    float s = 0.0f, s2 = 0.0f;
    for (int d = tid; d < EMBD; d += blockDim.x) { float v = x[d]; s += v; s2 += v * v; }
    for (int o = 16; o > 0; o >>= 1) {
        s += __shfl_down_sync(0xffffffffu, s, o);
        s2 += __shfl_down_sync(0xffffffffu, s2, o);
    }
    if ((tid & 31) == 0) { sA[tid >> 5] = s; sB[tid >> 5] = s2; }
    __syncthreads();
    int nw = blockDim.x >> 5;
    if (tid < 32) {
        s = (tid < nw) ? sA[tid] : 0.0f;
        s2 = (tid < nw) ? sB[tid] : 0.0f;
        for (int o = 16; o > 0; o >>= 1) {
            s += __shfl_down_sync(0xffffffffu, s, o);
            s2 += __shfl_down_sync(0xffffffffu, s2, o);
        }
        if (tid == 0) { sA[0] = s; sB[0] = s2; }
    }
    __syncthreads();
    float invD = 1.0f / (float)EMBD;
    float m = sA[0] * invD;
    float var = fmaxf(sB[0] * invD - m * m, 0.0f);
    float inv = rsqrtf(var + LNEPS);
    for (int d = tid; d < EMBD; d += blockDim.x) {
        float p = (x[d] - m) * inv * g[d] + b[d];
        __nv_bfloat16 h = __float2bfloat16(p);
        Phi[(size_t)r * EMBD + d] = h;
        Plo[(size_t)r * EMBD + d] = __float2bfloat16(p - __bfloat162float(h));
    }
}

// ---------------- fp32 SIMT GEMMs (SAGE / image path) ----------------
__global__ __launch_bounds__(256)
void gemm_nt_kernel(const float* __restrict__ A, int lda,
                    const float* __restrict__ B, int ldb,
                    float* __restrict__ C, int ldc,
                    int M, int N, int K,
                    const float* __restrict__ bias,
                    int accumulate, int do_relu) {
    __shared__ float As[8][128];
    __shared__ float Bs[8][128];
    int tid = threadIdx.x;
    int bm = blockIdx.y * 128;
    int bn = blockIdx.x * 128;
    int ty = tid >> 4, tx = tid & 15;
    float acc[8][8];
#pragma unroll
    for (int i = 0; i < 8; i++)
#pragma unroll
        for (int j = 0; j < 8; j++) acc[i][j] = 0.0f;
    for (int k0 = 0; k0 < K; k0 += 8) {
#pragma unroll
        for (int l = 0; l < 4; l++) {
            int e = tid + l * 256;
            int m = e & 127, kk = e >> 7;
            int gk = k0 + kk, gm = bm + m, gn = bn + m;
            As[kk][m] = (gm < M && gk < K) ? A[(size_t)gm * lda + gk] : 0.0f;
            Bs[kk][m] = (gn < N && gk < K) ? B[(size_t)gn * ldb + gk] : 0.0f;
        }
        __syncthreads();
#pragma unroll
        for (int kk = 0; kk < 8; kk++) {
            float a[8], b[8];
#pragma unroll
            for (int i = 0; i < 8; i++) a[i] = As[kk][ty * 8 + i];
#pragma unroll
            for (int j = 0; j < 8; j++) b[j] = Bs[kk][tx * 8 + j];
#pragma unroll
            for (int i = 0; i < 8; i++)
#pragma unroll
                for (int j = 0; j < 8; j++) acc[i][j] += a[i] * b[j];
        }
        __syncthreads();
    }
#pragma unroll
    for (int i = 0; i < 8; i++) {
        int m = bm + ty * 8 + i;
        if (m >= M) continue;
#pragma unroll
        for (int j = 0; j < 8; j++) {
            int n = bn + tx * 8 + j;
            if (n >= N) continue;
            float v = acc[i][j];
            if (bias) v += bias[n];
            if (accumulate) v += C[(size_t)m * ldc + n];
            if (do_relu) v = fmaxf(v, 0.0f);
            C[(size_t)m * ldc + n] = v;
        }
    }
}

__global__ __launch_bounds__(256)
void gemm_nn_kernel(const float* __restrict__ A, int lda,
                    const float* __restrict__ B, int ldb,
                    float* __restrict__ C, int ldc,
                    int M, int N, int K) {
    __shared__ float As[8][128];
    __shared__ float Bs[8][128];
    int tid = threadIdx.x;
    int bm = blockIdx.y * 128;
    int bn = blockIdx.x * 128;
    int ty = tid >> 4, tx = tid & 15;
    float acc[8][8];
#pragma unroll
    for (int i = 0; i < 8; i++)
#pragma unroll
        for (int j = 0; j < 8; j++) acc[i][j] = 0.0f;
    for (int k0 = 0; k0 < K; k0 += 8) {
#pragma unroll
        for (int l = 0; l < 4; l++) {
            int e = tid + l * 256;
            int m = e & 127, kk = e >> 7;
            int gk = k0 + kk, gm = bm + m, gn = bn + m;
            As[kk][m] = (gm < M && gk < K) ? A[(size_t)gm * lda + gk] : 0.0f;
            Bs[kk][m] = (gn < N && gk < K) ? B[(size_t)gk * ldb + gn] : 0.0f;
        }
        __syncthreads();
#pragma unroll
        for (int kk = 0; kk < 8; kk++) {
            float a[8], b[8];
#pragma unroll
            for (int i = 0; i < 8; i++) a[i] = As[kk][ty * 8 + i];
#pragma unroll
            for (int j = 0; j < 8; j++) b[j] = Bs[kk][tx * 8 + j];
#pragma unroll
            for (int i = 0; i < 8; i++)
#pragma unroll
                for (int j = 0; j < 8; j++) acc[i][j] += a[i] * b[j];
        }
        __syncthreads();
    }
#pragma unroll
    for (int i = 0; i < 8; i++) {
        int m = bm + ty * 8 + i;
        if (m >= M) continue;
#pragma unroll
        for (int j = 0; j < 8; j++) {
            int n = bn + tx * 8 + j;
            if (n >= N) continue;
            C[(size_t)m * ldc + n] = acc[i][j];
        }
    }
}

// ---------------- tensor-core split-bf16 GEMM ----------------
// C[M,N] = A[M,K] @ B[N,K]^T with A,B split into bf16 hi/lo; fp32 accumulate.
// AMODE 0: A read from fp32 global (Afp, lda).
// AMODE 1: A[r,k] = relu(PA[r/NOBJS, k] + PO[r%NOBJS, k]), lda = P1D row stride.
// B given pre-split (Bhi/Blo, ldb). CTA tile 128(M) x 160(N), K-tile 16, 8 warps.

__device__ __forceinline__ uint32_t smem_u32(const void* p) {
    return (uint32_t)__cvta_generic_to_shared(p);
}
__device__ __forceinline__ void ldmA4(uint32_t r[4], uint32_t addr) {
    asm volatile("ldmatrix.sync.aligned.m8n8.x4.shared.b16 {%0,%1,%2,%3},[%4];\n"
                 : "=r"(r[0]), "=r"(r[1]), "=r"(r[2]), "=r"(r[3]) : "r"(addr));
}
__device__ __forceinline__ void ldmB2(uint32_t r[2], uint32_t addr) {
    asm volatile("ldmatrix.sync.aligned.m8n8.x2.shared.b16 {%0,%1},[%2];\n"
                 : "=r"(r[0]), "=r"(r[1]) : "r"(addr));
}
__device__ __forceinline__ void mma16816(float d[4], const uint32_t a[4],
                                         const uint32_t b[2]) {
    asm volatile(
        "mma.sync.aligned.m16n8k16.row.col.f32.bf16.bf16.f32 "
        "{%0,%1,%2,%3},{%4,%5,%6,%7},{%8,%9},{%0,%1,%2,%3};\n"
        : "+f"(d[0]), "+f"(d[1]), "+f"(d[2]), "+f"(d[3])
        : "r"(a[0]), "r"(a[1]), "r"(a[2]), "r"(a[3]), "r"(b[0]), "r"(b[1]));
}
__device__ __forceinline__ void cp16(uint32_t dst, const void* src) {
    asm volatile("cp.async.cg.shared.global [%0], [%1], 16;\n" :: "r"(dst), "l"(src));
}
__device__ __forceinline__ void cp_commit() { asm volatile("cp.async.commit_group;\n"); }
__device__ __forceinline__ void cp_wait0()  { asm volatile("cp.async.wait_group 0;\n"); }

#define MT 128
#define NT 160
#define LDK 24     // 16 + 8 pad (conflict-free ldmatrix)

template <int AMODE>
__global__ __launch_bounds__(256, 1)
void mma_gemm_kernel(const float* __restrict__ Afp, int lda,
                     const float* __restrict__ PA, const float* __restrict__ PO,
                     const __nv_bfloat16* __restrict__ Bhi,
                     const __nv_bfloat16* __restrict__ Blo, int ldb,
                     float* __restrict__ C, int ldc,
                     int M, int K, const float* __restrict__ bias) {
    extern __shared__ __nv_bfloat16 smem[];
    __nv_bfloat16* sAhi = smem;                     // 2 * MT * LDK
    __nv_bfloat16* sAlo = sAhi + 2 * MT * LDK;
    __nv_bfloat16* sBhi = sAlo + 2 * MT * LDK;      // 2 * NT * LDK
    __nv_bfloat16* sBlo = sBhi + 2 * NT * LDK;

    const int tid = threadIdx.x;
    const int warp = tid >> 5;
    const int lane = tid & 31;
    const int bm = blockIdx.y * MT;
    const int bn = blockIdx.x * NT;
    const int wm = warp & 1;      // 2 warps along M
    const int wn = warp >> 1;     // 4 warps along N

    // A-loader meta: thread covers row ar, k-halve ah (8 elems)
    const int ar = tid >> 1;
    const int ah = (tid & 1) * 8;
    const int arow = bm + ar;
    const bool avalid = arow < M;
    int aidx = 0, oidx = 0;
    if (AMODE == 1) { aidx = arow / NOBJS; oidx = arow - aidx * NOBJS; }

    float acc[4][5][4];
#pragma unroll
    for (int i = 0; i < 4; i++)
#pragma unroll
        for (int j = 0; j < 5; j++)
#pragma unroll
            for (int c = 0; c < 4; c++) acc[i][j][c] = 0.0f;

    float va[8];
    auto load_A = [&](int kb) {
        if (avalid) {
            if (AMODE == 0) {
                const float4* p = (const float4*)(Afp + (size_t)arow * lda + kb + ah);
                float4 x0 = p[0], x1 = p[1];
                va[0] = x0.x; va[1] = x0.y; va[2] = x0.z; va[3] = x0.w;
                va[4] = x1.x; va[5] = x1.y; va[6] = x1.z; va[7] = x1.w;
            } else {
                const float4* pa = (const float4*)(PA + (size_t)aidx * lda + kb + ah);
                const float4* po = (const float4*)(PO + (size_t)oidx * lda + kb + ah);
                float4 a0 = pa[0], a1 = pa[1], o0 = po[0], o1 = po[1];
                va[0] = fmaxf(a0.x + o0.x, 0.0f); va[1] = fmaxf(a0.y + o0.y, 0.0f);
                va[2] = fmaxf(a0.z + o0.z, 0.0f); va[3] = fmaxf(a0.w + o0.w, 0.0f);
                va[4] = fmaxf(a1.x + o1.x, 0.0f); va[5] = fmaxf(a1.y + o1.y, 0.0f);
                va[6] = fmaxf(a1.z + o1.z, 0.0f); va[7] = fmaxf(a1.w + o1.w, 0.0f);
            }
        } else {
#pragma unroll
            for (int j = 0; j < 8; j++) va[j] = 0.0f;
        }
    };
    auto sts_A = [&](int buf) {
        union { __nv_bfloat16 b[8]; uint4 u; } Uh, Ul;
#pragma unroll
        for (int j = 0; j < 8; j++) {
            __nv_bfloat16 h = __float2bfloat16(va[j]);
            Uh.b[j] = h;
            Ul.b[j] = __float2bfloat16(va[j] - __bfloat162float(h));
        }
        *(uint4*)(sAhi + buf * MT * LDK + ar * LDK + ah) = Uh.u;
        *(uint4*)(sAlo + buf * MT * LDK + ar * LDK + ah) = Ul.u;
    };
    auto load_B = [&](int kb, int buf) {
        for (int i = tid; i < 2 * NT * 2; i += 256) {   // 640 vec8 loads
            int hi = (i < 2 * NT) ? 1 : 0;
            int v = hi ? i : (i - 2 * NT);
            int row = v >> 1;
            int hh = (v & 1) * 8;
            const __nv_bfloat16* src = hi ? Bhi : Blo;
            __nv_bfloat16* dst = (hi ? sBhi : sBlo) + buf * NT * LDK + row * LDK + hh;
            cp16(smem_u32(dst), src + (size_t)(bn + row) * ldb + kb + hh);
        }
    };

    const int NKT = K / 16;
    // prologue
    load_A(0);
    sts_A(0);
    load_B(0, 0);
    cp_commit();
    cp_wait0();
    __syncthreads();

    for (int kt = 0; kt < NKT; kt++) {
        const int cur = kt & 1;
        const int nxt = cur ^ 1;
        const bool hasnext = (kt + 1) < NKT;
        if (hasnext) {
            load_A((kt + 1) * 16);
            load_B((kt + 1) * 16, nxt);
            cp_commit();
        }
        // fragments
        uint32_t afh[4][4], afl[4][4];
        const int arowf = lane & 15;
        const int akf = ((lane >> 4) & 1) * 8;
#pragma unroll
        for (int mi = 0; mi < 4; mi++) {
            int m0 = wm * 64 + mi * 16;
            ldmA4(afh[mi], smem_u32(sAhi + cur * MT * LDK + (m0 + arowf) * LDK + akf));
            ldmA4(afl[mi], smem_u32(sAlo + cur * MT * LDK + (m0 + arowf) * LDK + akf));
        }
        uint32_t bfh[5][2], bfl[5][2];
        const int brow = lane & 7;
        const int bkf = ((lane >> 3) & 1) * 8;
#pragma unroll
        for (int ni = 0; ni < 5; ni++) {
            int n0 = wn * 40 + ni * 8;
            ldmB2(bfh[ni], smem_u32(sBhi + cur * NT * LDK + (n0 + brow) * LDK + bkf));
            ldmB2(bfl[ni], smem_u32(sBlo + cur * NT * LDK + (n0 + brow) * LDK + bkf));
        }
#pragma unroll
        for (int mi = 0; mi < 4; mi++)
#pragma unroll
            for (int ni = 0; ni < 5; ni++) {
                mma16816(acc[mi][ni], afh[mi], bfh[ni]);
                mma16816(acc[mi][ni], afh[mi], bfl[ni]);
                mma16816(acc[mi][ni], afl[mi], bfh[ni]);
            }
        if (hasnext) sts_A(nxt);
        cp_wait0();
        __syncthreads();
    }

    // epilogue
#pragma unroll
    for (int mi = 0; mi < 4; mi++) {
#pragma unroll
        for (int ni = 0; ni < 5; ni++) {
            int m0 = bm + wm * 64 + mi * 16 + (lane >> 2);
            int n0 = bn + wn * 40 + ni * 8 + (lane & 3) * 2;
            float b0 = bias ? bias[n0] : 0.0f;
            float b1 = bias ? bias[n0 + 1] : 0.0f;
            if (m0 < M) {
                float2 v = make_float2(acc[mi][ni][0] + b0, acc[mi][ni][1] + b1);
                *(float2*)(C + (size_t)m0 * ldc + n0) = v;
            }
            if (m0 + 8 < M) {
                float2 v = make_float2(acc[mi][ni][2] + b0, acc[mi][ni][3] + b1);
                *(float2*)(C + (size_t)(m0 + 8) * ldc + n0) = v;
            }
        }
    }
}

// ---------------- host side ----------------
static inline dim3 gemm_grid(int M, int N) {
    return dim3((N + 127) / 128, (M + 127) / 128);
}

extern "C" void kernel_launch(void* const* d_in, const int* in_sizes, int n_in,
                              void* d_out, int out_size) {
    const float* img   = (const float*)d_in[0];
    const float* nodes = (const float*)d_in[1];
    const int*   esrc  = (const int*)d_in[2];
    const int*   edst  = (const int*)d_in[3];
    const float* W1l   = (const float*)d_in[4];
    const float* b1    = (const float*)d_in[5];
    const float* W1r   = (const float*)d_in[6];
    const float* W2l   = (const float*)d_in[7];
    const float* b2    = (const float*)d_in[8];
    const float* W2r   = (const float*)d_in[9];
    const float* Wp1   = (const float*)d_in[10];
    const float* bp1   = (const float*)d_in[11];
    const float* Wp2   = (const float*)d_in[12];
    const float* bp2   = (const float*)d_in[13];
    const float* gp    = (const float*)d_in[14];
    const float* bpn   = (const float*)d_in[15];
    const float* Wi1   = (const float*)d_in[16];
    const float* bi1   = (const float*)d_in[17];
    const float* Wi2   = (const float*)d_in[18];
    const float* bi2   = (const float*)d_in[19];
    const float* Wi3   = (const float*)d_in[20];
    const float* bi3   = (const float*)d_in[21];
    const float* gi    = (const float*)d_in[22];
    const float* bin_  = (const float*)d_in[23];
    float* out = (float*)d_out;

    void* sp = nullptr;
    cudaGetSymbolAddress(&sp, g_scratch);
    float* S0 = (float*)sp;
    void* p;
    cudaGetSymbolAddress(&p, g_wp2hi); __nv_bfloat16* wp2hi = (__nv_bfloat16*)p;
    cudaGetSymbolAddress(&p, g_wp2lo); __nv_bfloat16* wp2lo = (__nv_bfloat16*)p;
    cudaGetSymbolAddress(&p, g_phi);   __nv_bfloat16* Phi   = (__nv_bfloat16*)p;
    cudaGetSymbolAddress(&p, g_plo);   __nv_bfloat16* Plo   = (__nv_bfloat16*)p;

    float* adj   = S0 + OFF_ADJ;
    float* mean1 = S0 + OFF_MEAN1;
    float* h     = S0 + OFF_H;
    float* mean2 = S0 + OFF_MEAN2;
    float* on    = S0 + OFF_ON;
    float* PA    = S0 + OFF_PA;
    float* PO    = S0 + OFF_PO;
    float* Q     = S0 + OFF_Q;
    float* i1    = S0 + OFF_I1;
    float* i2    = S0 + OFF_I2;
    float* i3    = S0 + OFF_I3;

    const int smem_bytes = (2 * MT * LDK * 2 + 2 * NT * LDK * 2) * 2; // 55296
    cudaFuncSetAttribute(mma_gemm_kernel<0>,
                         cudaFuncAttributeMaxDynamicSharedMemorySize, smem_bytes);
    cudaFuncSetAttribute(mma_gemm_kernel<1>,
                         cudaFuncAttributeMaxDynamicSharedMemorySize, smem_bytes);

    // ---- graph: dense normalized adjacency ----
    {
        int n = NNODES * NNODES;
        zero_kernel<<<(n + 255) / 256, 256>>>(adj, n);
        edge_count_kernel<<<(NEDGES + 255) / 256, 256>>>(esrc, edst, adj);
        row_norm_kernel<<<NNODES, 256>>>(adj);
    }

    // ---- SAGE layers (fp32 SIMT) ----
    gemm_nn_kernel<<<gemm_grid(NNODES, DIN), 256>>>(adj, NNODES, nodes, DIN,
                                                    mean1, DIN, NNODES, DIN, NNODES);
    gemm_nt_kernel<<<gemm_grid(NNODES, DHID), 256>>>(mean1, DIN, W1l, DIN,
                                                     h, DHID, NNODES, DHID, DIN,
                                                     b1, 0, 0);
    gemm_nt_kernel<<<gemm_grid(NNODES, DHID), 256>>>(nodes, DIN, W1r, DIN,
                                                     h, DHID, NNODES, DHID, DIN,
                                                     nullptr, 1, 1);
    gemm_nn_kernel<<<gemm_grid(NNODES, DHID), 256>>>(adj, NNODES, h, DHID,
                                                     mean2, DHID, NNODES, DHID, NNODES);
    gemm_nt_kernel<<<gemm_grid(NNODES, DNODE), 256>>>(mean2, DHID, W2l, DHID,
                                                      on, DNODE, NNODES, DNODE, DHID,
                                                      b2, 0, 0);
    gemm_nt_kernel<<<gemm_grid(NNODES, DNODE), 256>>>(h, DHID, W2r, DHID,
                                                      on, DNODE, NNODES, DNODE, DHID,
                                                      nullptr, 1, 0);

    // ---- factored pair tables ----
    const float* attr = on;
    const float* obj  = on + (size_t)NATTRS * DNODE;
    gemm_nt_kernel<<<gemm_grid(NATTRS, P1D), 256>>>(attr, DNODE, Wp1, 2 * DNODE,
                                                    PA, P1D, NATTRS, P1D, DNODE,
                                                    bp1, 0, 0);
    gemm_nt_kernel<<<gemm_grid(NOBJS, P1D), 256>>>(obj, DNODE, Wp1 + DNODE, 2 * DNODE,
                                                   PO, P1D, NOBJS, P1D, DNODE,
                                                   nullptr, 0, 0);

    // ---- split Wp2 to bf16 hi/lo ----
    {
        int n = EMBD * P1D;
        split_kernel<<<(n + 255) / 256, 256>>>(Wp2, wp2hi, wp2lo, n);
    }

    // ---- Q = relu(PA_i + PO_j) @ Wp2^T + bp2  (tensor core, fused S) ----
    {
        dim3 grid(EMBD / NT, (NPAIRS + MT - 1) / MT);   // 5 x 782
        mma_gemm_kernel<1><<<grid, 256, smem_bytes>>>(nullptr, P1D, PA, PO,
                                                      wp2hi, wp2lo, P1D,
                                                      Q, EMBD, NPAIRS, P1D, bp2);
    }

    // ---- LN rows of Q -> P split bf16 ----
    ln_split_kernel<<<NPAIRS, 256>>>(Q, gp, bpn, Phi, Plo);

    // ---- image MLP (fp32 SIMT) ----
    gemm_nt_kernel<<<gemm_grid(BATCH, 768), 256>>>(img, FEATD, Wi1, FEATD,
                                                   i1, 768, BATCH, 768, FEATD,
                                                   bi1, 0, 1);
    gemm_nt_kernel<<<gemm_grid(BATCH, 1000), 256>>>(i1, 768, Wi2, 768,
                                                    i2, 1000, BATCH, 1000, 768,
                                                    bi2, 0, 1);
    gemm_nt_kernel<<<gemm_grid(BATCH, EMBD), 256>>>(i2, 1000, Wi3, 1000,
                                                    i3, EMBD, BATCH, EMBD, 1000,
                                                    bi3, 0, 0);
    ln_kernel<<<BATCH, 256>>>(i3, gi, bin_, EMBD);

    // ---- out = iLN @ P^T  (tensor core) ----
    {
        dim3 grid(NPAIRS / NT, BATCH / MT);   // 625 x 2
        mma_gemm_kernel<0><<<grid, 256, smem_bytes>>>(i3, EMBD, nullptr, nullptr,
                                                      Phi, Plo, EMBD,
                                                      out, NPAIRS, BATCH, EMBD, nullptr);
    }
}

// round 5
// speedup vs baseline: 2.1358x; 1.1263x over previous
#include <cuda_runtime.h>
#include <cuda_fp16.h>
#include <cstdint>

#define NATTRS 250
#define NOBJS  400
#define NNODES 650
#define NEDGES 100000
#define DIN    512
#define DHID   4096
#define DNODE  512
#define FEATD  2048
#define EMBD   800
#define BATCH  256
#define P1D    1200
#define NPAIRS (NATTRS * NOBJS)   /* 100000 */
#define LNEPS  1e-5f

// ---------------- scratch layout (single __device__ global; no allocs) ----------------
#define OFF_ADJ    0ull
#define OFF_MEAN1  (OFF_ADJ   + (size_t)NNODES * NNODES)
#define OFF_H      (OFF_MEAN1 + (size_t)NNODES * DIN)
#define OFF_MEAN2  (OFF_H     + (size_t)NNODES * DHID)
#define OFF_ON     (OFF_MEAN2 + (size_t)NNODES * DHID)
#define OFF_PA     (OFF_ON    + (size_t)NNODES * DNODE)
#define OFF_PO     (OFF_PA    + (size_t)NATTRS * P1D)
#define OFF_Q      (OFF_PO    + (size_t)NOBJS  * P1D)
#define OFF_I1     (OFF_Q     + (size_t)NPAIRS * EMBD)
#define OFF_I2     (OFF_I1    + (size_t)BATCH * 768)
#define OFF_I3     (OFF_I2    + (size_t)BATCH * 1000)
#define SCRATCH_ELEMS (OFF_I3 + (size_t)BATCH * EMBD)

__device__ float g_scratch[SCRATCH_ELEMS];
__device__ __half g_wp2h[(size_t)EMBD * P1D];
__device__ __half g_ph[(size_t)NPAIRS * EMBD];

// ---------------- small kernels ----------------
__global__ void zero_kernel(float* p, int n) {
    int i = blockIdx.x * blockDim.x + threadIdx.x;
    if (i < n) p[i] = 0.0f;
}

__global__ void edge_count_kernel(const int* __restrict__ src,
                                  const int* __restrict__ dst,
                                  float* __restrict__ adj) {
    int e = blockIdx.x * blockDim.x + threadIdx.x;
    if (e < NEDGES) atomicAdd(&adj[(size_t)dst[e] * NNODES + src[e]], 1.0f);
}

__global__ void row_norm_kernel(float* __restrict__ adj) {
    __shared__ float sbuf[32];
    int r = blockIdx.x;
    int tid = threadIdx.x;
    float s = 0.0f;
    float* row = adj + (size_t)r * NNODES;
    for (int c = tid; c < NNODES; c += blockDim.x) s += row[c];
    for (int o = 16; o > 0; o >>= 1) s += __shfl_down_sync(0xffffffffu, s, o);
    if ((tid & 31) == 0) sbuf[tid >> 5] = s;
    __syncthreads();
    int nw = blockDim.x >> 5;
    if (tid < 32) {
        s = (tid < nw) ? sbuf[tid] : 0.0f;
        for (int o = 16; o > 0; o >>= 1) s += __shfl_down_sync(0xffffffffu, s, o);
        if (tid == 0) sbuf[0] = s;
    }
    __syncthreads();
    float inv = 1.0f / fmaxf(sbuf[0], 1.0f);
    for (int c = tid; c < NNODES; c += blockDim.x) row[c] *= inv;
}

// fp32 -> fp16
__global__ void tohalf_kernel(const float* __restrict__ x,
                              __half* __restrict__ y, int n) {
    int i = blockIdx.x * blockDim.x + threadIdx.x;
    if (i < n) y[i] = __float2half_rn(x[i]);
}

// in-place LayerNorm (fp32)
__global__ void ln_kernel(float* __restrict__ X,
                          const float* __restrict__ g,
                          const float* __restrict__ b, int D) {
    __shared__ float sA[32], sB[32];
    int r = blockIdx.x;
    int tid = threadIdx.x;
    float* x = X + (size_t)r * D;
    float s = 0.0f, s2 = 0.0f;
    for (int d = tid; d < D; d += blockDim.x) { float v = x[d]; s += v; s2 += v * v; }
    for (int o = 16; o > 0; o >>= 1) {
        s += __shfl_down_sync(0xffffffffu, s, o);
        s2 += __shfl_down_sync(0xffffffffu, s2, o);
    }
    if ((tid & 31) == 0) { sA[tid >> 5] = s; sB[tid >> 5] = s2; }
    __syncthreads();
    int nw = blockDim.x >> 5;
    if (tid < 32) {
        s = (tid < nw) ? sA[tid] : 0.0f;
        s2 = (tid < nw) ? sB[tid] : 0.0f;
        for (int o = 16; o > 0; o >>= 1) {
            s += __shfl_down_sync(0xffffffffu, s, o);
            s2 += __shfl_down_sync(0xffffffffu, s2, o);
        }
        if (tid == 0) { sA[0] = s; sB[0] = s2; }
    }
    __syncthreads();
    float invD = 1.0f / (float)D;
    float m = sA[0] * invD;
    float var = fmaxf(sB[0] * invD - m * m, 0.0f);
    float inv = rsqrtf(var + LNEPS);
    for (int d = tid; d < D; d += blockDim.x)
        x[d] = (x[d] - m) * inv * g[d] + b[d];
}

// LayerNorm of Q rows -> write fp16 P
__global__ void ln_half_kernel(const float* __restrict__ Q,
                               const float* __restrict__ g,
                               const float* __restrict__ b,
                               __half* __restrict__ Ph) {
    __shared__ float sA[32], sB[32];
    int r = blockIdx.x;
    int tid = threadIdx.x;
    const float* x = Q + (size_t)r * EMBD;
    float s = 0.0f, s2 = 0.0f;
    for (int d = tid; d < EMBD; d += blockDim.x) { float v = x[d]; s += v; s2 += v * v; }
    for (int o = 16; o > 0; o >>= 1) {
        s += __shfl_down_sync(0xffffffffu, s, o);
        s2 += __shfl_down_sync(0xffffffffu, s2, o);
    }
    if ((tid & 31) == 0) { sA[tid >> 5] = s; sB[tid >> 5] = s2; }
    __syncthreads();
    int nw = blockDim.x >> 5;
    if (tid < 32) {
        s = (tid < nw) ? sA[tid] : 0.0f;
        s2 = (tid < nw) ? sB[tid] : 0.0f;
        for (int o = 16; o > 0; o >>= 1) {
            s += __shfl_down_sync(0xffffffffu, s, o);
            s2 += __shfl_down_sync(0xffffffffu, s2, o);
        }
        if (tid == 0) { sA[0] = s; sB[0] = s2; }
    }
    __syncthreads();
    float invD = 1.0f / (float)EMBD;
    float m = sA[0] * invD;
    float var = fmaxf(sB[0] * invD - m * m, 0.0f);
    float inv = rsqrtf(var + LNEPS);
    for (int d = tid; d < EMBD; d += blockDim.x) {
        float p = (x[d] - m) * inv * g[d] + b[d];
        Ph[(size_t)r * EMBD + d] = __float2half_rn(p);
    }
}

// ---------------- fp32 SIMT GEMMs (SAGE / image path) ----------------
__global__ __launch_bounds__(256)
void gemm_nt_kernel(const float* __restrict__ A, int lda,
                    const float* __restrict__ B, int ldb,
                    float* __restrict__ C, int ldc,
                    int M, int N, int K,
                    const float* __restrict__ bias,
                    int accumulate, int do_relu) {
    __shared__ float As[8][128];
    __shared__ float Bs[8][128];
    int tid = threadIdx.x;
    int bm = blockIdx.y * 128;
    int bn = blockIdx.x * 128;
    int ty = tid >> 4, tx = tid & 15;
    float acc[8][8];
#pragma unroll
    for (int i = 0; i < 8; i++)
#pragma unroll
        for (int j = 0; j < 8; j++) acc[i][j] = 0.0f;
    for (int k0 = 0; k0 < K; k0 += 8) {
#pragma unroll
        for (int l = 0; l < 4; l++) {
            int e = tid + l * 256;
            int m = e & 127, kk = e >> 7;
            int gk = k0 + kk, gm = bm + m, gn = bn + m;
            As[kk][m] = (gm < M && gk < K) ? A[(size_t)gm * lda + gk] : 0.0f;
            Bs[kk][m] = (gn < N && gk < K) ? B[(size_t)gn * ldb + gk] : 0.0f;
        }
        __syncthreads();
#pragma unroll
        for (int kk = 0; kk < 8; kk++) {
            float a[8], b[8];
#pragma unroll
            for (int i = 0; i < 8; i++) a[i] = As[kk][ty * 8 + i];
#pragma unroll
            for (int j = 0; j < 8; j++) b[j] = Bs[kk][tx * 8 + j];
#pragma unroll
            for (int i = 0; i < 8; i++)
#pragma unroll
                for (int j = 0; j < 8; j++) acc[i][j] += a[i] * b[j];
        }
        __syncthreads();
    }
#pragma unroll
    for (int i = 0; i < 8; i++) {
        int m = bm + ty * 8 + i;
        if (m >= M) continue;
#pragma unroll
        for (int j = 0; j < 8; j++) {
            int n = bn + tx * 8 + j;
            if (n >= N) continue;
            float v = acc[i][j];
            if (bias) v += bias[n];
            if (accumulate) v += C[(size_t)m * ldc + n];
            if (do_relu) v = fmaxf(v, 0.0f);
            C[(size_t)m * ldc + n] = v;
        }
    }
}

__global__ __launch_bounds__(256)
void gemm_nn_kernel(const float* __restrict__ A, int lda,
                    const float* __restrict__ B, int ldb,
                    float* __restrict__ C, int ldc,
                    int M, int N, int K) {
    __shared__ float As[8][128];
    __shared__ float Bs[8][128];
    int tid = threadIdx.x;
    int bm = blockIdx.y * 128;
    int bn = blockIdx.x * 128;
    int ty = tid >> 4, tx = tid & 15;
    float acc[8][8];
#pragma unroll
    for (int i = 0; i < 8; i++)
#pragma unroll
        for (int j = 0; j < 8; j++) acc[i][j] = 0.0f;
    for (int k0 = 0; k0 < K; k0 += 8) {
#pragma unroll
        for (int l = 0; l < 4; l++) {
            int e = tid + l * 256;
            int m = e & 127, kk = e >> 7;
            int gk = k0 + kk, gm = bm + m, gn = bn + m;
            As[kk][m] = (gm < M && gk < K) ? A[(size_t)gm * lda + gk] : 0.0f;
            Bs[kk][m] = (gn < N && gk < K) ? B[(size_t)gk * ldb + gn] : 0.0f;
        }
        __syncthreads();
#pragma unroll
        for (int kk = 0; kk < 8; kk++) {
            float a[8], b[8];
#pragma unroll
            for (int i = 0; i < 8; i++) a[i] = As[kk][ty * 8 + i];
#pragma unroll
            for (int j = 0; j < 8; j++) b[j] = Bs[kk][tx * 8 + j];
#pragma unroll
            for (int i = 0; i < 8; i++)
#pragma unroll
                for (int j = 0; j < 8; j++) acc[i][j] += a[i] * b[j];
        }
        __syncthreads();
    }
#pragma unroll
    for (int i = 0; i < 8; i++) {
        int m = bm + ty * 8 + i;
        if (m >= M) continue;
#pragma unroll
        for (int j = 0; j < 8; j++) {
            int n = bn + tx * 8 + j;
            if (n >= N) continue;
            C[(size_t)m * ldc + n] = acc[i][j];
        }
    }
}

// ---------------- tensor-core fp16 GEMM (single-term) ----------------
// C[M,N] = A[M,K] @ B[N,K]^T, fp16 inputs, fp32 accumulate.
// AMODE 0: A read from fp32 global (converted in-loader).
// AMODE 1: A[r,k] = relu(PA[r/NOBJS, k] + PO[r%NOBJS, k]), lda = P1D.
// B pre-converted fp16 (Bh, ldb). CTA tile 128(M) x 160(N), K-tile 16, 8 warps.

__device__ __forceinline__ uint32_t smem_u32(const void* p) {
    return (uint32_t)__cvta_generic_to_shared(p);
}
__device__ __forceinline__ void ldmA4(uint32_t r[4], uint32_t addr) {
    asm volatile("ldmatrix.sync.aligned.m8n8.x4.shared.b16 {%0,%1,%2,%3},[%4];\n"
                 : "=r"(r[0]), "=r"(r[1]), "=r"(r[2]), "=r"(r[3]) : "r"(addr));
}
__device__ __forceinline__ void ldmB2(uint32_t r[2], uint32_t addr) {
    asm volatile("ldmatrix.sync.aligned.m8n8.x2.shared.b16 {%0,%1},[%2];\n"
                 : "=r"(r[0]), "=r"(r[1]) : "r"(addr));
}
__device__ __forceinline__ void mma16816(float d[4], const uint32_t a[4],
                                         const uint32_t b[2]) {
    asm volatile(
        "mma.sync.aligned.m16n8k16.row.col.f32.f16.f16.f32 "
        "{%0,%1,%2,%3},{%4,%5,%6,%7},{%8,%9},{%0,%1,%2,%3};\n"
        : "+f"(d[0]), "+f"(d[1]), "+f"(d[2]), "+f"(d[3])
        : "r"(a[0]), "r"(a[1]), "r"(a[2]), "r"(a[3]), "r"(b[0]), "r"(b[1]));
}
__device__ __forceinline__ void cp16(uint32_t dst, const void* src) {
    asm volatile("cp.async.cg.shared.global [%0], [%1], 16;\n" :: "r"(dst), "l"(src));
}
__device__ __forceinline__ void cp_commit() { asm volatile("cp.async.commit_group;\n"); }
__device__ __forceinline__ void cp_wait0()  { asm volatile("cp.async.wait_group 0;\n"); }

#define MT 128
#define NT 160
#define LDK 24     // 16 + 8 pad (conflict-free ldmatrix)

template <int AMODE>
__global__ __launch_bounds__(256, 1)
void mma_gemm_kernel(const float* __restrict__ Afp, int lda,
                     const float* __restrict__ PA, const float* __restrict__ PO,
                     const __half* __restrict__ Bh, int ldb,
                     float* __restrict__ C, int ldc,
                     int M, int K, const float* __restrict__ bias) {
    extern __shared__ __half smem[];
    __half* sA = smem;                    // 2 * MT * LDK
    __half* sB = sA + 2 * MT * LDK;       // 2 * NT * LDK

    const int tid = threadIdx.x;
    const int warp = tid >> 5;
    const int lane = tid & 31;
    const int bm = blockIdx.y * MT;
    const int bn = blockIdx.x * NT;
    const int wm = warp & 1;      // 2 warps along M
    const int wn = warp >> 1;     // 4 warps along N

    // A-loader meta: thread covers row ar, k-halve ah (8 elems)
    const int ar = tid >> 1;
    const int ah = (tid & 1) * 8;
    const int arow = bm + ar;
    const bool avalid = arow < M;
    int aidx = 0, oidx = 0;
    if (AMODE == 1) { aidx = arow / NOBJS; oidx = arow - aidx * NOBJS; }

    float acc[4][5][4];
#pragma unroll
    for (int i = 0; i < 4; i++)
#pragma unroll
        for (int j = 0; j < 5; j++)
#pragma unroll
            for (int c = 0; c < 4; c++) acc[i][j][c] = 0.0f;

    float va[8];
    auto load_A = [&](int kb) {
        if (avalid) {
            if (AMODE == 0) {
                const float4* p = (const float4*)(Afp + (size_t)arow * lda + kb + ah);
                float4 x0 = p[0], x1 = p[1];
                va[0] = x0.x; va[1] = x0.y; va[2] = x0.z; va[3] = x0.w;
                va[4] = x1.x; va[5] = x1.y; va[6] = x1.z; va[7] = x1.w;
            } else {
                const float4* pa = (const float4*)(PA + (size_t)aidx * lda + kb + ah);
                const float4* po = (const float4*)(PO + (size_t)oidx * lda + kb + ah);
                float4 a0 = pa[0], a1 = pa[1], o0 = po[0], o1 = po[1];
                va[0] = fmaxf(a0.x + o0.x, 0.0f); va[1] = fmaxf(a0.y + o0.y, 0.0f);
                va[2] = fmaxf(a0.z + o0.z, 0.0f); va[3] = fmaxf(a0.w + o0.w, 0.0f);
                va[4] = fmaxf(a1.x + o1.x, 0.0f); va[5] = fmaxf(a1.y + o1.y, 0.0f);
                va[6] = fmaxf(a1.z + o1.z, 0.0f); va[7] = fmaxf(a1.w + o1.w, 0.0f);
            }
        } else {
#pragma unroll
            for (int j = 0; j < 8; j++) va[j] = 0.0f;
        }
    };
    auto sts_A = [&](int buf) {
        union { __half b[8]; uint4 u; } U;
#pragma unroll
        for (int j = 0; j < 8; j++) U.b[j] = __float2half_rn(va[j]);
        *(uint4*)(sA + buf * MT * LDK + ar * LDK + ah) = U.u;
    };
    auto load_B = [&](int kb, int buf) {
        for (int i = tid; i < NT * 2; i += 256) {   // 320 vec8 loads
            int row = i >> 1;
            int hh = (i & 1) * 8;
            __half* dst = sB + buf * NT * LDK + row * LDK + hh;
            cp16(smem_u32(dst), Bh + (size_t)(bn + row) * ldb + kb + hh);
        }
    };

    const int NKT = K / 16;
    // prologue
    load_A(0);
    sts_A(0);
    load_B(0, 0);
    cp_commit();
    cp_wait0();
    __syncthreads();

    for (int kt = 0; kt < NKT; kt++) {
        const int cur = kt & 1;
        const int nxt = cur ^ 1;
        const bool hasnext = (kt + 1) < NKT;
        if (hasnext) {
            load_A((kt + 1) * 16);
            load_B((kt + 1) * 16, nxt);
            cp_commit();
        }
        // fragments
        uint32_t af[4][4];
        const int arowf = lane & 15;
        const int akf = ((lane >> 4) & 1) * 8;
#pragma unroll
        for (int mi = 0; mi < 4; mi++) {
            int m0 = wm * 64 + mi * 16;
            ldmA4(af[mi], smem_u32(sA + cur * MT * LDK + (m0 + arowf) * LDK + akf));
        }
        uint32_t bf[5][2];
        const int brow = lane & 7;
        const int bkf = ((lane >> 3) & 1) * 8;
#pragma unroll
        for (int ni = 0; ni < 5; ni++) {
            int n0 = wn * 40 + ni * 8;
            ldmB2(bf[ni], smem_u32(sB + cur * NT * LDK + (n0 + brow) * LDK + bkf));
        }
#pragma unroll
        for (int mi = 0; mi < 4; mi++)
#pragma unroll
            for (int ni = 0; ni < 5; ni++)
                mma16816(acc[mi][ni], af[mi], bf[ni]);
        if (hasnext) sts_A(nxt);
        cp_wait0();
        __syncthreads();
    }

    // epilogue
#pragma unroll
    for (int mi = 0; mi < 4; mi++) {
#pragma unroll
        for (int ni = 0; ni < 5; ni++) {
            int m0 = bm + wm * 64 + mi * 16 + (lane >> 2);
            int n0 = bn + wn * 40 + ni * 8 + (lane & 3) * 2;
            float b0 = bias ? bias[n0] : 0.0f;
            float b1 = bias ? bias[n0 + 1] : 0.0f;
            if (m0 < M) {
                float2 v = make_float2(acc[mi][ni][0] + b0, acc[mi][ni][1] + b1);
                *(float2*)(C + (size_t)m0 * ldc + n0) = v;
            }
            if (m0 + 8 < M) {
                float2 v = make_float2(acc[mi][ni][2] + b0, acc[mi][ni][3] + b1);
                *(float2*)(C + (size_t)(m0 + 8) * ldc + n0) = v;
            }
        }
    }
}

// ---------------- host side ----------------
static inline dim3 gemm_grid(int M, int N) {
    return dim3((N + 127) / 128, (M + 127) / 128);
}

extern "C" void kernel_launch(void* const* d_in, const int* in_sizes, int n_in,
                              void* d_out, int out_size) {
    const float* img   = (const float*)d_in[0];
    const float* nodes = (const float*)d_in[1];
    const int*   esrc  = (const int*)d_in[2];
    const int*   edst  = (const int*)d_in[3];
    const float* W1l   = (const float*)d_in[4];
    const float* b1    = (const float*)d_in[5];
    const float* W1r   = (const float*)d_in[6];
    const float* W2l   = (const float*)d_in[7];
    const float* b2    = (const float*)d_in[8];
    const float* W2r   = (const float*)d_in[9];
    const float* Wp1   = (const float*)d_in[10];
    const float* bp1   = (const float*)d_in[11];
    const float* Wp2   = (const float*)d_in[12];
    const float* bp2   = (const float*)d_in[13];
    const float* gp    = (const float*)d_in[14];
    const float* bpn   = (const float*)d_in[15];
    const float* Wi1   = (const float*)d_in[16];
    const float* bi1   = (const float*)d_in[17];
    const float* Wi2   = (const float*)d_in[18];
    const float* bi2   = (const float*)d_in[19];
    const float* Wi3   = (const float*)d_in[20];
    const float* bi3   = (const float*)d_in[21];
    const float* gi    = (const float*)d_in[22];
    const float* bin_  = (const float*)d_in[23];
    float* out = (float*)d_out;

    void* sp = nullptr;
    cudaGetSymbolAddress(&sp, g_scratch);
    float* S0 = (float*)sp;
    void* p;
    cudaGetSymbolAddress(&p, g_wp2h); __half* wp2h = (__half*)p;
    cudaGetSymbolAddress(&p, g_ph);   __half* Ph   = (__half*)p;

    float* adj   = S0 + OFF_ADJ;
    float* mean1 = S0 + OFF_MEAN1;
    float* h     = S0 + OFF_H;
    float* mean2 = S0 + OFF_MEAN2;
    float* on    = S0 + OFF_ON;
    float* PA    = S0 + OFF_PA;
    float* PO    = S0 + OFF_PO;
    float* Q     = S0 + OFF_Q;
    float* i1    = S0 + OFF_I1;
    float* i2    = S0 + OFF_I2;
    float* i3    = S0 + OFF_I3;

    const int smem_bytes = (2 * MT * LDK + 2 * NT * LDK) * 2;   // 27648
    cudaFuncSetAttribute(mma_gemm_kernel<0>,
                         cudaFuncAttributeMaxDynamicSharedMemorySize, smem_bytes);
    cudaFuncSetAttribute(mma_gemm_kernel<1>,
                         cudaFuncAttributeMaxDynamicSharedMemorySize, smem_bytes);

    // ---- graph: dense normalized adjacency ----
    {
        int n = NNODES * NNODES;
        zero_kernel<<<(n + 255) / 256, 256>>>(adj, n);
        edge_count_kernel<<<(NEDGES + 255) / 256, 256>>>(esrc, edst, adj);
        row_norm_kernel<<<NNODES, 256>>>(adj);
    }

    // ---- SAGE layers (fp32 SIMT) ----
    gemm_nn_kernel<<<gemm_grid(NNODES, DIN), 256>>>(adj, NNODES, nodes, DIN,
                                                    mean1, DIN, NNODES, DIN, NNODES);
    gemm_nt_kernel<<<gemm_grid(NNODES, DHID), 256>>>(mean1, DIN, W1l, DIN,
                                                     h, DHID, NNODES, DHID, DIN,
                                                     b1, 0, 0);
    gemm_nt_kernel<<<gemm_grid(NNODES, DHID), 256>>>(nodes, DIN, W1r, DIN,
                                                     h, DHID, NNODES, DHID, DIN,
                                                     nullptr, 1, 1);
    gemm_nn_kernel<<<gemm_grid(NNODES, DHID), 256>>>(adj, NNODES, h, DHID,
                                                     mean2, DHID, NNODES, DHID, NNODES);
    gemm_nt_kernel<<<gemm_grid(NNODES, DNODE), 256>>>(mean2, DHID, W2l, DHID,
                                                      on, DNODE, NNODES, DNODE, DHID,
                                                      b2, 0, 0);
    gemm_nt_kernel<<<gemm_grid(NNODES, DNODE), 256>>>(h, DHID, W2r, DHID,
                                                      on, DNODE, NNODES, DNODE, DHID,
                                                      nullptr, 1, 0);

    // ---- factored pair tables ----
    const float* attr = on;
    const float* obj  = on + (size_t)NATTRS * DNODE;
    gemm_nt_kernel<<<gemm_grid(NATTRS, P1D), 256>>>(attr, DNODE, Wp1, 2 * DNODE,
                                                    PA, P1D, NATTRS, P1D, DNODE,
                                                    bp1, 0, 0);
    gemm_nt_kernel<<<gemm_grid(NOBJS, P1D), 256>>>(obj, DNODE, Wp1 + DNODE, 2 * DNODE,
                                                   PO, P1D, NOBJS, P1D, DNODE,
                                                   nullptr, 0, 0);

    // ---- Wp2 -> fp16 ----
    {
        int n = EMBD * P1D;
        tohalf_kernel<<<(n + 255) / 256, 256>>>(Wp2, wp2h, n);
    }

    // ---- Q = relu(PA_i + PO_j) @ Wp2^T + bp2  (fp16 tensor core, fused S) ----
    {
        dim3 grid(EMBD / NT, (NPAIRS + MT - 1) / MT);   // 5 x 782
        mma_gemm_kernel<1><<<grid, 256, smem_bytes>>>(nullptr, P1D, PA, PO,
                                                      wp2h, P1D,
                                                      Q, EMBD, NPAIRS, P1D, bp2);
    }

    // ---- LN rows of Q -> P fp16 ----
    ln_half_kernel<<<NPAIRS, 256>>>(Q, gp, bpn, Ph);

    // ---- image MLP (fp32 SIMT) ----
    gemm_nt_kernel<<<gemm_grid(BATCH, 768), 256>>>(img, FEATD, Wi1, FEATD,
                                                   i1, 768, BATCH, 768, FEATD,
                                                   bi1, 0, 1);
    gemm_nt_kernel<<<gemm_grid(BATCH, 1000), 256>>>(i1, 768, Wi2, 768,
                                                    i2, 1000, BATCH, 1000, 768,
                                                    bi2, 0, 1);
    gemm_nt_kernel<<<gemm_grid(BATCH, EMBD), 256>>>(i2, 1000, Wi3, 1000,
                                                    i3, EMBD, BATCH, EMBD, 1000,
                                                    bi3, 0, 0);
    ln_kernel<<<BATCH, 256>>>(i3, gi, bin_, EMBD);

    // ---- out = iLN @ P^T  (fp16 tensor core) ----
    {
        dim3 grid(NPAIRS / NT, BATCH / MT);   // 625 x 2
        mma_gemm_kernel<0><<<grid, 256, smem_bytes>>>(i3, EMBD, nullptr, nullptr,
                                                      Ph, EMBD,
                                                      out, NPAIRS, BATCH, EMBD, nullptr);
    }
}

// round 6
// speedup vs baseline: 5.8401x; 2.7344x over previous
#include <cuda_runtime.h>
#include <cuda_fp16.h>
#include <cuda_bf16.h>
#include <cstdint>

#define NATTRS 250
#define NOBJS  400
#define NNODES 650
#define NEDGES 100000
#define DIN    512
#define DHID   4096
#define DNODE  512
#define FEATD  2048
#define EMBD   800
#define BATCH  256
#define P1D    1200
#define NPAIRS (NATTRS * NOBJS)
#define LNEPS  1e-5f

// ---------------- scratch (single __device__ global; no allocs) ----------------
#define OFF_ADJ    0ull
#define OFF_MEAN1  (OFF_ADJ   + (size_t)NNODES * NNODES)
#define OFF_H      (OFF_MEAN1 + (size_t)NNODES * DIN)
#define OFF_T2     (OFF_H     + (size_t)NNODES * DHID)
#define OFF_ON     (OFF_T2    + (size_t)NNODES * 1024)
#define OFF_PP     (OFF_ON    + (size_t)NNODES * DNODE)
#define OFF_Q      (OFF_PP    + (size_t)NNODES * P1D)
#define OFF_I1     (OFF_Q     + (size_t)NPAIRS * EMBD)
#define OFF_I2     (OFF_I1    + (size_t)BATCH * 768)
#define OFF_I3     (OFF_I2    + (size_t)BATCH * 1024)
#define SCRATCH_ELEMS (OFF_I3 + (size_t)BATCH * EMBD)

__device__ float g_scratch[SCRATCH_ELEMS];

// split-bf16 weight buffers
__device__ uint16_t g_w1c_hi[(size_t)DHID * 1024];
__device__ uint16_t g_w1c_lo[(size_t)DHID * 1024];
__device__ uint16_t g_w2c_hi[(size_t)1024 * DHID];
__device__ uint16_t g_w2c_lo[(size_t)1024 * DHID];
__device__ uint16_t g_wp1_hi[(size_t)P1D * 1024];
__device__ uint16_t g_wp1_lo[(size_t)P1D * 1024];
__device__ uint16_t g_wi1_hi[(size_t)768 * FEATD];
__device__ uint16_t g_wi1_lo[(size_t)768 * FEATD];
__device__ uint16_t g_wi2_hi[(size_t)1000 * 768];
__device__ uint16_t g_wi2_lo[(size_t)1000 * 768];
__device__ uint16_t g_wi3_hi[(size_t)EMBD * 1024];
__device__ uint16_t g_wi3_lo[(size_t)EMBD * 1024];
// fp16 buffers
__device__ uint16_t g_wp2h[(size_t)EMBD * P1D];
__device__ uint16_t g_ph[(size_t)NPAIRS * EMBD];

// ---------------- small kernels ----------------
__global__ void zero_kernel(float* p, int n) {
    int i = blockIdx.x * blockDim.x + threadIdx.x;
    if (i < n) p[i] = 0.0f;
}

__global__ void edge_count_kernel(const int* __restrict__ src,
                                  const int* __restrict__ dst,
                                  float* __restrict__ adj) {
    int e = blockIdx.x * blockDim.x + threadIdx.x;
    if (e < NEDGES) atomicAdd(&adj[(size_t)dst[e] * NNODES + src[e]], 1.0f);
}

__global__ void row_norm_kernel(float* __restrict__ adj) {
    __shared__ float sbuf[32];
    int r = blockIdx.x;
    int tid = threadIdx.x;
    float s = 0.0f;
    float* row = adj + (size_t)r * NNODES;
    for (int c = tid; c < NNODES; c += blockDim.x) s += row[c];
    for (int o = 16; o > 0; o >>= 1) s += __shfl_down_sync(0xffffffffu, s, o);
    if ((tid & 31) == 0) sbuf[tid >> 5] = s;
    __syncthreads();
    int nw = blockDim.x >> 5;
    if (tid < 32) {
        s = (tid < nw) ? sbuf[tid] : 0.0f;
        for (int o = 16; o > 0; o >>= 1) s += __shfl_down_sync(0xffffffffu, s, o);
        if (tid == 0) sbuf[0] = s;
    }
    __syncthreads();
    float inv = 1.0f / fmaxf(sbuf[0], 1.0f);
    for (int c = tid; c < NNODES; c += blockDim.x) row[c] *= inv;
}

// split-concat to bf16 hi/lo:
// out[n*ldo + k] = k < K1 ? X1[n*K1+k] : (k < K1+K2 ? X2[n*K2 + k-K1] : 0)
__global__ void splitcat_kernel(const float* __restrict__ X1, int K1,
                                const float* __restrict__ X2, int K2,
                                uint16_t* __restrict__ hi, uint16_t* __restrict__ lo,
                                int ldo, int Nrows) {
    int i = blockIdx.x * blockDim.x + threadIdx.x;
    if (i >= Nrows * ldo) return;
    int n = i / ldo, k = i - n * ldo;
    float v = 0.0f;
    if (k < K1) v = X1[(size_t)n * K1 + k];
    else if (k < K1 + K2) v = X2[(size_t)n * K2 + (k - K1)];
    __nv_bfloat16 h = __float2bfloat16(v);
    hi[i] = __bfloat16_as_ushort(h);
    lo[i] = __bfloat16_as_ushort(__float2bfloat16(v - __bfloat162float(h)));
}

__global__ void tohalf_kernel(const float* __restrict__ x,
                              uint16_t* __restrict__ y, int n) {
    int i = blockIdx.x * blockDim.x + threadIdx.x;
    if (i < n) y[i] = __half_as_ushort(__float2half_rn(x[i]));
}

// in-place LayerNorm (fp32)
__global__ void ln_kernel(float* __restrict__ X,
                          const float* __restrict__ g,
                          const float* __restrict__ b, int D) {
    __shared__ float sA[32], sB[32];
    int r = blockIdx.x;
    int tid = threadIdx.x;
    float* x = X + (size_t)r * D;
    float s = 0.0f, s2 = 0.0f;
    for (int d = tid; d < D; d += blockDim.x) { float v = x[d]; s += v; s2 += v * v; }
    for (int o = 16; o > 0; o >>= 1) {
        s += __shfl_down_sync(0xffffffffu, s, o);
        s2 += __shfl_down_sync(0xffffffffu, s2, o);
    }
    if ((tid & 31) == 0) { sA[tid >> 5] = s; sB[tid >> 5] = s2; }
    __syncthreads();
    int nw = blockDim.x >> 5;
    if (tid < 32) {
        s = (tid < nw) ? sA[tid] : 0.0f;
        s2 = (tid < nw) ? sB[tid] : 0.0f;
        for (int o = 16; o > 0; o >>= 1) {
            s += __shfl_down_sync(0xffffffffu, s, o);
            s2 += __shfl_down_sync(0xffffffffu, s2, o);
        }
        if (tid == 0) { sA[0] = s; sB[0] = s2; }
    }
    __syncthreads();
    float invD = 1.0f / (float)D;
    float m = sA[0] * invD;
    float var = fmaxf(sB[0] * invD - m * m, 0.0f);
    float inv = rsqrtf(var + LNEPS);
    for (int d = tid; d < D; d += blockDim.x)
        x[d] = (x[d] - m) * inv * g[d] + b[d];
}

// LayerNorm of Q rows -> fp16 P
__global__ void ln_half_kernel(const float* __restrict__ Q,
                               const float* __restrict__ g,
                               const float* __restrict__ b,
                               uint16_t* __restrict__ Ph) {
    __shared__ float sA[32], sB[32];
    int r = blockIdx.x;
    int tid = threadIdx.x;
    const float* x = Q + (size_t)r * EMBD;
    float s = 0.0f, s2 = 0.0f;
    for (int d = tid; d < EMBD; d += blockDim.x) { float v = x[d]; s += v; s2 += v * v; }
    for (int o = 16; o > 0; o >>= 1) {
        s += __shfl_down_sync(0xffffffffu, s, o);
        s2 += __shfl_down_sync(0xffffffffu, s2, o);
    }
    if ((tid & 31) == 0) { sA[tid >> 5] = s; sB[tid >> 5] = s2; }
    __syncthreads();
    int nw = blockDim.x >> 5;
    if (tid < 32) {
        s = (tid < nw) ? sA[tid] : 0.0f;
        s2 = (tid < nw) ? sB[tid] : 0.0f;
        for (int o = 16; o > 0; o >>= 1) {
            s += __shfl_down_sync(0xffffffffu, s, o);
            s2 += __shfl_down_sync(0xffffffffu, s2, o);
        }
        if (tid == 0) { sA[0] = s; sB[0] = s2; }
    }
    __syncthreads();
    float invD = 1.0f / (float)EMBD;
    float m = sA[0] * invD;
    float var = fmaxf(sB[0] * invD - m * m, 0.0f);
    float inv = rsqrtf(var + LNEPS);
    for (int d = tid; d < EMBD; d += blockDim.x) {
        float p = (x[d] - m) * inv * g[d] + b[d];
        Ph[(size_t)r * EMBD + d] = __half_as_ushort(__float2half_rn(p));
    }
}

// ---------------- small fp32 NN gemm (64x64 tiles) ----------------
// C[m,n] = sum_k A[m,k]*B[k*ldb+n] (+bias[n]) (+extra[m*lde+n])
__global__ __launch_bounds__(256)
void nn_small_kernel(const float* __restrict__ A, int lda,
                     const float* __restrict__ B, int ldb,
                     const float* __restrict__ bias,
                     const float* __restrict__ extra, int lde,
                     float* __restrict__ C, int ldc,
                     int M, int N, int K) {
    __shared__ float As[16][68];
    __shared__ float Bs[16][68];
    int tid = threadIdx.x;
    int bm = blockIdx.y * 64, bn = blockIdx.x * 64;
    int tx = tid & 15, ty = tid >> 4;
    float acc[4][4];
#pragma unroll
    for (int i = 0; i < 4; i++)
#pragma unroll
        for (int j = 0; j < 4; j++) acc[i][j] = 0.0f;
    for (int k0 = 0; k0 < K; k0 += 16) {
        for (int e = tid; e < 1024; e += 256) {
            int row = e & 63, kk = e >> 6;
            int gm = bm + row, gk = k0 + kk, gn = bn + row;
            As[kk][row] = (gm < M && gk < K) ? A[(size_t)gm * lda + gk] : 0.0f;
            Bs[kk][row] = (gn < N && gk < K) ? B[(size_t)gk * ldb + gn] : 0.0f;
        }
        __syncthreads();
#pragma unroll
        for (int kk = 0; kk < 16; kk++) {
            float a[4], b[4];
#pragma unroll
            for (int i = 0; i < 4; i++) a[i] = As[kk][ty * 4 + i];
#pragma unroll
            for (int j = 0; j < 4; j++) b[j] = Bs[kk][tx * 4 + j];
#pragma unroll
            for (int i = 0; i < 4; i++)
#pragma unroll
                for (int j = 0; j < 4; j++) acc[i][j] += a[i] * b[j];
        }
        __syncthreads();
    }
#pragma unroll
    for (int i = 0; i < 4; i++) {
        int m = bm + ty * 4 + i;
        if (m >= M) continue;
#pragma unroll
        for (int j = 0; j < 4; j++) {
            int n = bn + tx * 4 + j;
            if (n >= N) continue;
            float v = acc[i][j];
            if (bias) v += bias[n];
            if (extra) v += extra[(size_t)m * lde + n];
            C[(size_t)m * ldc + n] = v;
        }
    }
}

// ================= generalized tensor-core GEMM =================
// C[M,NB] = A[M,K] @ B[NB,K]^T  (+bias), optional relu.
// SPLIT=1: 3-term split-bf16 (fp32-like). SPLIT=0: single-term fp16.
// AMODE 0: A = A1 (fp32, lda1)
// AMODE 1: A[r,k] = relu(A1[r/NOBJS,k] + A2[r%NOBJS,k] + bias1[k])
// AMODE 2: A[r,k] = k<K1 ? A1[r,k] : A2[r,k-K1]
// AMODE 3: A[r,k] = r<NATTRS ? (k<K1 ? A1[r,k] : 0) : (k>=K1 ? A1[r,k-K1] : 0)
// CTA tile: 128(M) x NT_(N), K-stage 32 (2 sub-k16).

__device__ __forceinline__ uint32_t smem_u32(const void* p) {
    return (uint32_t)__cvta_generic_to_shared(p);
}
__device__ __forceinline__ void ldmA4(uint32_t r[4], uint32_t addr) {
    asm volatile("ldmatrix.sync.aligned.m8n8.x4.shared.b16 {%0,%1,%2,%3},[%4];\n"
                 : "=r"(r[0]), "=r"(r[1]), "=r"(r[2]), "=r"(r[3]) : "r"(addr));
}
__device__ __forceinline__ void ldmB2(uint32_t r[2], uint32_t addr) {
    asm volatile("ldmatrix.sync.aligned.m8n8.x2.shared.b16 {%0,%1},[%2];\n"
                 : "=r"(r[0]), "=r"(r[1]) : "r"(addr));
}
__device__ __forceinline__ void mma_f16(float d[4], const uint32_t a[4],
                                        const uint32_t b[2]) {
    asm volatile(
        "mma.sync.aligned.m16n8k16.row.col.f32.f16.f16.f32 "
        "{%0,%1,%2,%3},{%4,%5,%6,%7},{%8,%9},{%0,%1,%2,%3};\n"
        : "+f"(d[0]), "+f"(d[1]), "+f"(d[2]), "+f"(d[3])
        : "r"(a[0]), "r"(a[1]), "r"(a[2]), "r"(a[3]), "r"(b[0]), "r"(b[1]));
}
__device__ __forceinline__ void mma_bf16(float d[4], const uint32_t a[4],
                                         const uint32_t b[2]) {
    asm volatile(
        "mma.sync.aligned.m16n8k16.row.col.f32.bf16.bf16.f32 "
        "{%0,%1,%2,%3},{%4,%5,%6,%7},{%8,%9},{%0,%1,%2,%3};\n"
        : "+f"(d[0]), "+f"(d[1]), "+f"(d[2]), "+f"(d[3])
        : "r"(a[0]), "r"(a[1]), "r"(a[2]), "r"(a[3]), "r"(b[0]), "r"(b[1]));
}
__device__ __forceinline__ void cp16(uint32_t dst, const void* src) {
    asm volatile("cp.async.cg.shared.global [%0], [%1], 16;\n" :: "r"(dst), "l"(src));
}
__device__ __forceinline__ void cp_commit() { asm volatile("cp.async.commit_group;\n"); }
__device__ __forceinline__ void cp_wait0()  { asm volatile("cp.async.wait_group 0;\n"); }

template <int AMODE, int SPLIT, int RELU, int NT_>
__global__ __launch_bounds__(256)
void mma2_kernel(const float* __restrict__ A1, int lda1,
                 const float* __restrict__ A2, int lda2, int K1,
                 const uint16_t* __restrict__ Bhi,
                 const uint16_t* __restrict__ Blo, int ldb,
                 float* __restrict__ C, int ldc,
                 int M, int NB, int K,
                 const float* __restrict__ bias,
                 const float* __restrict__ bias1) {
    constexpr int NI   = NT_ / 32;           // ldmB2 count per warp
    constexpr int ASZ  = 128 * 80;           // bytes per A plane (40 halfs/row pad)
    constexpr int BSZ  = NT_ * 80;
    constexpr int NPLA = SPLIT ? 2 : 1;
    constexpr int STRIDE = NPLA * (ASZ + BSZ);
    constexpr int AhiO = 0;
    constexpr int AloO = ASZ;
    constexpr int BhiO = NPLA * ASZ;
    constexpr int BloO = NPLA * ASZ + BSZ;

    extern __shared__ char smem[];
    const uint32_t sb = smem_u32(smem);
    const int tid = threadIdx.x;
    const int warp = tid >> 5;
    const int lane = tid & 31;
    const int bm = blockIdx.y * 128;
    const int bn = blockIdx.x * NT_;
    const int wm = warp & 1;
    const int wn = warp >> 1;

    const int ar = tid >> 1;
    const int ah = (tid & 1) * 16;           // float offset within k32 stage
    const int arow = bm + ar;
    const bool avalid = arow < M;
    const float* pA = nullptr;
    const float* pA2 = nullptr;
    bool attr_row = true;
    if (AMODE == 0) {
        pA = A1 + (size_t)(avalid ? arow : 0) * lda1;
    } else if (AMODE == 1) {
        int ai = avalid ? (arow / NOBJS) : 0;
        int oi = avalid ? (arow - ai * NOBJS) : 0;
        pA = A1 + (size_t)ai * lda1;
        pA2 = A2 + (size_t)oi * lda2;
    } else if (AMODE == 2) {
        pA = A1 + (size_t)(avalid ? arow : 0) * lda1;
        pA2 = A2 + (size_t)(avalid ? arow : 0) * lda2;
    } else {
        pA = A1 + (size_t)(avalid ? arow : 0) * lda1;
        attr_row = arow < NATTRS;
    }

    float acc[4][NI][4];
#pragma unroll
    for (int i = 0; i < 4; i++)
#pragma unroll
        for (int j = 0; j < NI; j++)
#pragma unroll
            for (int c = 0; c < 4; c++) acc[i][j][c] = 0.0f;

    float va[16];
    auto load_A = [&](int kb) {
        int k0 = kb + ah;
        bool ok = avalid && (k0 < K);
#pragma unroll
        for (int q = 0; q < 16; q++) va[q] = 0.0f;
        if (ok) {
            if (AMODE == 0) {
#pragma unroll
                for (int g = 0; g < 4; g++) {
                    float4 x = *(const float4*)(pA + k0 + g * 4);
                    va[g*4+0] = x.x; va[g*4+1] = x.y; va[g*4+2] = x.z; va[g*4+3] = x.w;
                }
            } else if (AMODE == 1) {
#pragma unroll
                for (int g = 0; g < 4; g++) {
                    float4 a = *(const float4*)(pA  + k0 + g * 4);
                    float4 o = *(const float4*)(pA2 + k0 + g * 4);
                    float4 b = *(const float4*)(bias1 + k0 + g * 4);
                    va[g*4+0] = fmaxf(a.x + o.x + b.x, 0.0f);
                    va[g*4+1] = fmaxf(a.y + o.y + b.y, 0.0f);
                    va[g*4+2] = fmaxf(a.z + o.z + b.z, 0.0f);
                    va[g*4+3] = fmaxf(a.w + o.w + b.w, 0.0f);
                }
            } else if (AMODE == 2) {
                const float* src = (k0 < K1) ? (pA + k0) : (pA2 + (k0 - K1));
#pragma unroll
                for (int g = 0; g < 4; g++) {
                    float4 x = *(const float4*)(src + g * 4);
                    va[g*4+0] = x.x; va[g*4+1] = x.y; va[g*4+2] = x.z; va[g*4+3] = x.w;
                }
            } else {
                bool use = attr_row ? (k0 < K1) : (k0 >= K1);
                if (use) {
                    const float* src = attr_row ? (pA + k0) : (pA + (k0 - K1));
#pragma unroll
                    for (int g = 0; g < 4; g++) {
                        float4 x = *(const float4*)(src + g * 4);
                        va[g*4+0] = x.x; va[g*4+1] = x.y; va[g*4+2] = x.z; va[g*4+3] = x.w;
                    }
                }
            }
        }
    };
    auto sts_A = [&](int buf) {
        const int base = buf * STRIDE;
#pragma unroll
        for (int g = 0; g < 2; g++) {       // two 8-elem groups
            union { uint16_t b[8]; uint4 u; } Uh, Ul;
#pragma unroll
            for (int q = 0; q < 8; q++) {
                float v = va[g * 8 + q];
                if (SPLIT) {
                    __nv_bfloat16 h = __float2bfloat16(v);
                    Uh.b[q] = __bfloat16_as_ushort(h);
                    Ul.b[q] = __bfloat16_as_ushort(__float2bfloat16(v - __bfloat162float(h)));
                } else {
                    Uh.b[q] = __half_as_ushort(__float2half_rn(v));
                }
            }
            uint32_t off = (uint32_t)(ar * 80 + (ah + g * 8) * 2);
            *(uint4*)(smem + base + AhiO + off) = Uh.u;
            if (SPLIT) *(uint4*)(smem + base + AloO + off) = Ul.u;
        }
    };
    auto load_B = [&](int kb, int buf) {
        const int base = buf * STRIDE;
        const int total = NT_ * 4 * NPLA;
        for (int i = tid; i < total; i += 256) {
            int plane = (i >= NT_ * 4) ? 1 : 0;
            int v = i - plane * NT_ * 4;
            int row = v >> 2;
            int c = v & 3;
            int k0 = kb + c * 8;
            uint32_t doff = (uint32_t)(base + (plane ? BloO : BhiO) + row * 80 + c * 16);
            if ((bn + row) < NB && k0 < K) {
                const uint16_t* src = (plane ? Blo : Bhi) + (size_t)(bn + row) * ldb + k0;
                cp16(sb + doff, src);
            } else {
                *(uint4*)(smem + doff) = make_uint4(0u, 0u, 0u, 0u);
            }
        }
    };

    const int NST = (K + 31) / 32;
    load_A(0);
    sts_A(0);
    load_B(0, 0);
    cp_commit();
    cp_wait0();
    __syncthreads();

    const int arowf = lane & 15;
    const int akf = ((lane >> 4) & 1) * 8;
    const int brow = lane & 7;
    const int bkf = ((lane >> 3) & 1) * 8;

    for (int st = 0; st < NST; st++) {
        const int cur = st & 1;
        const int nxt = cur ^ 1;
        const bool hasnext = (st + 1) < NST;
        if (hasnext) {
            load_A((st + 1) * 32);
            load_B((st + 1) * 32, nxt);
            cp_commit();
        }
        const int cbase = cur * STRIDE;
#pragma unroll
        for (int sub = 0; sub < 2; sub++) {
            if (st * 32 + sub * 16 >= K) break;
            const int kcol = (sub * 16 + akf) * 2;
            const int kcolb = (sub * 16 + bkf) * 2;
            uint32_t afh[4][4], afl[4][4];
#pragma unroll
            for (int mi = 0; mi < 4; mi++) {
                int m0 = wm * 64 + mi * 16;
                ldmA4(afh[mi], sb + cbase + AhiO + (m0 + arowf) * 80 + kcol);
                if (SPLIT)
                    ldmA4(afl[mi], sb + cbase + AloO + (m0 + arowf) * 80 + kcol);
            }
            uint32_t bfh[NI][2], bfl[NI][2];
#pragma unroll
            for (int ni = 0; ni < NI; ni++) {
                int n0 = wn * (NT_ / 4) + ni * 8;
                ldmB2(bfh[ni], sb + cbase + BhiO + (n0 + brow) * 80 + kcolb);
                if (SPLIT)
                    ldmB2(bfl[ni], sb + cbase + BloO + (n0 + brow) * 80 + kcolb);
            }
#pragma unroll
            for (int mi = 0; mi < 4; mi++)
#pragma unroll
                for (int ni = 0; ni < NI; ni++) {
                    if (SPLIT) {
                        mma_bf16(acc[mi][ni], afh[mi], bfh[ni]);
                        mma_bf16(acc[mi][ni], afh[mi], bfl[ni]);
                        mma_bf16(acc[mi][ni], afl[mi], bfh[ni]);
                    } else {
                        mma_f16(acc[mi][ni], afh[mi], bfh[ni]);
                    }
                }
        }
        if (hasnext) sts_A(nxt);
        cp_wait0();
        __syncthreads();
    }

    // epilogue
#pragma unroll
    for (int mi = 0; mi < 4; mi++) {
#pragma unroll
        for (int ni = 0; ni < NI; ni++) {
            int m0 = bm + wm * 64 + mi * 16 + (lane >> 2);
            int n0 = bn + wn * (NT_ / 4) + ni * 8 + (lane & 3) * 2;
            if (n0 >= NB) continue;
            float b0 = bias ? bias[n0] : 0.0f;
            float b1v = bias ? bias[n0 + 1] : 0.0f;
            float v0 = acc[mi][ni][0] + b0, v1 = acc[mi][ni][1] + b1v;
            float v2 = acc[mi][ni][2] + b0, v3 = acc[mi][ni][3] + b1v;
            if (RELU) {
                v0 = fmaxf(v0, 0.0f); v1 = fmaxf(v1, 0.0f);
                v2 = fmaxf(v2, 0.0f); v3 = fmaxf(v3, 0.0f);
            }
            if (m0 < M) *(float2*)(C + (size_t)m0 * ldc + n0) = make_float2(v0, v1);
            if (m0 + 8 < M) *(float2*)(C + (size_t)(m0 + 8) * ldc + n0) = make_float2(v2, v3);
        }
    }
}

// ---------------- host ----------------
static inline int ceildiv(int a, int b) { return (a + b - 1) / b; }

extern "C" void kernel_launch(void* const* d_in, const int* in_sizes, int n_in,
                              void* d_out, int out_size) {
    const float* img   = (const float*)d_in[0];
    const float* nodes = (const float*)d_in[1];
    const int*   esrc  = (const int*)d_in[2];
    const int*   edst  = (const int*)d_in[3];
    const float* W1l   = (const float*)d_in[4];
    const float* b1    = (const float*)d_in[5];
    const float* W1r   = (const float*)d_in[6];
    const float* W2l   = (const float*)d_in[7];
    const float* b2    = (const float*)d_in[8];
    const float* W2r   = (const float*)d_in[9];
    const float* Wp1   = (const float*)d_in[10];
    const float* bp1   = (const float*)d_in[11];
    const float* Wp2   = (const float*)d_in[12];
    const float* bp2   = (const float*)d_in[13];
    const float* gp    = (const float*)d_in[14];
    const float* bpn   = (const float*)d_in[15];
    const float* Wi1   = (const float*)d_in[16];
    const float* bi1   = (const float*)d_in[17];
    const float* Wi2   = (const float*)d_in[18];
    const float* bi2   = (const float*)d_in[19];
    const float* Wi3   = (const float*)d_in[20];
    const float* bi3   = (const float*)d_in[21];
    const float* gi    = (const float*)d_in[22];
    const float* bin_  = (const float*)d_in[23];
    float* out = (float*)d_out;

    void* p;
    cudaGetSymbolAddress(&p, g_scratch);
    float* S0 = (float*)p;
    uint16_t *w1h, *w1l_, *w2h, *w2l_, *wp1h, *wp1l, *wi1h, *wi1l,
             *wi2h, *wi2l, *wi3h, *wi3l, *wp2h, *Ph;
    cudaGetSymbolAddress(&p, g_w1c_hi); w1h  = (uint16_t*)p;
    cudaGetSymbolAddress(&p, g_w1c_lo); w1l_ = (uint16_t*)p;
    cudaGetSymbolAddress(&p, g_w2c_hi); w2h  = (uint16_t*)p;
    cudaGetSymbolAddress(&p, g_w2c_lo); w2l_ = (uint16_t*)p;
    cudaGetSymbolAddress(&p, g_wp1_hi); wp1h = (uint16_t*)p;
    cudaGetSymbolAddress(&p, g_wp1_lo); wp1l = (uint16_t*)p;
    cudaGetSymbolAddress(&p, g_wi1_hi); wi1h = (uint16_t*)p;
    cudaGetSymbolAddress(&p, g_wi1_lo); wi1l = (uint16_t*)p;
    cudaGetSymbolAddress(&p, g_wi2_hi); wi2h = (uint16_t*)p;
    cudaGetSymbolAddress(&p, g_wi2_lo); wi2l = (uint16_t*)p;
    cudaGetSymbolAddress(&p, g_wi3_hi); wi3h = (uint16_t*)p;
    cudaGetSymbolAddress(&p, g_wi3_lo); wi3l = (uint16_t*)p;
    cudaGetSymbolAddress(&p, g_wp2h);   wp2h = (uint16_t*)p;
    cudaGetSymbolAddress(&p, g_ph);     Ph   = (uint16_t*)p;

    float* adj   = S0 + OFF_ADJ;
    float* mean1 = S0 + OFF_MEAN1;
    float* h     = S0 + OFF_H;
    float* T2    = S0 + OFF_T2;
    float* on    = S0 + OFF_ON;
    float* PP    = S0 + OFF_PP;
    float* Q     = S0 + OFF_Q;
    float* i1    = S0 + OFF_I1;
    float* i2    = S0 + OFF_I2;
    float* i3    = S0 + OFF_I3;

    // smem sizes per instantiation
    const int SM_S128 = 2 * (2 * (128 * 80) + 2 * (128 * 80));  // 81920
    const int SM_S160 = 2 * (2 * (128 * 80) + 2 * (160 * 80));  // 92160
    const int SM_F160 = 2 * ((128 * 80) + (160 * 80));          // 46080
    cudaFuncSetAttribute(mma2_kernel<2,1,1,128>, cudaFuncAttributeMaxDynamicSharedMemorySize, SM_S128);
    cudaFuncSetAttribute(mma2_kernel<0,1,0,128>, cudaFuncAttributeMaxDynamicSharedMemorySize, SM_S128);
    cudaFuncSetAttribute(mma2_kernel<0,1,1,128>, cudaFuncAttributeMaxDynamicSharedMemorySize, SM_S128);
    cudaFuncSetAttribute(mma2_kernel<3,1,0,160>, cudaFuncAttributeMaxDynamicSharedMemorySize, SM_S160);
    cudaFuncSetAttribute(mma2_kernel<0,1,0,160>, cudaFuncAttributeMaxDynamicSharedMemorySize, SM_S160);
    cudaFuncSetAttribute(mma2_kernel<1,0,0,160>, cudaFuncAttributeMaxDynamicSharedMemorySize, SM_F160);
    cudaFuncSetAttribute(mma2_kernel<0,0,0,160>, cudaFuncAttributeMaxDynamicSharedMemorySize, SM_F160);

    // ---- graph: dense normalized adjacency ----
    {
        int n = NNODES * NNODES;
        zero_kernel<<<(n + 255) / 256, 256>>>(adj, n);
        edge_count_kernel<<<(NEDGES + 255) / 256, 256>>>(esrc, edst, adj);
        row_norm_kernel<<<NNODES, 256>>>(adj);
    }

    // ---- weight prep (split to bf16 hi/lo; Wp2 to fp16) ----
    {
        int n;
        n = DHID * 1024;
        splitcat_kernel<<<(n + 255) / 256, 256>>>(W1l, DIN, W1r, DIN, w1h, w1l_, 1024, DHID);
        n = 512 * DHID;
        splitcat_kernel<<<(n + 255) / 256, 256>>>(W2l, DHID, nullptr, 0, w2h, w2l_, DHID, 512);
        splitcat_kernel<<<(n + 255) / 256, 256>>>(W2r, DHID, nullptr, 0,
                                                  w2h + (size_t)512 * DHID,
                                                  w2l_ + (size_t)512 * DHID, DHID, 512);
        n = P1D * 1024;
        splitcat_kernel<<<(n + 255) / 256, 256>>>(Wp1, 1024, nullptr, 0, wp1h, wp1l, 1024, P1D);
        n = 768 * FEATD;
        splitcat_kernel<<<(n + 255) / 256, 256>>>(Wi1, FEATD, nullptr, 0, wi1h, wi1l, FEATD, 768);
        n = 1000 * 768;
        splitcat_kernel<<<(n + 255) / 256, 256>>>(Wi2, 768, nullptr, 0, wi2h, wi2l, 768, 1000);
        n = EMBD * 1024;
        splitcat_kernel<<<(n + 255) / 256, 256>>>(Wi3, 1000, nullptr, 0, wi3h, wi3l, 1024, EMBD);
        n = EMBD * P1D;
        tohalf_kernel<<<(n + 255) / 256, 256>>>(Wp2, wp2h, n);
    }

    // ---- mean1 = adj @ nodes  [650x512] ----
    nn_small_kernel<<<dim3(DIN / 64, ceildiv(NNODES, 64)), 256>>>(
        adj, NNODES, nodes, DIN, nullptr, nullptr, 0, mean1, DIN, NNODES, DIN, NNODES);

    // ---- h = relu([mean1|nodes] @ [W1l|W1r]^T + b1)  M=650,N=4096,K=1024 ----
    mma2_kernel<2,1,1,128><<<dim3(DHID / 128, ceildiv(NNODES, 128)), 256, SM_S128>>>(
        mean1, DIN, nodes, DIN, DIN, w1h, w1l_, 1024, h, DHID, NNODES, DHID, 1024, b1, nullptr);

    // ---- T2 = h @ [W2l;W2r]^T  M=650,N=1024,K=4096 ----
    mma2_kernel<0,1,0,128><<<dim3(1024 / 128, ceildiv(NNODES, 128)), 256, SM_S128>>>(
        h, DHID, nullptr, 0, 0, w2h, w2l_, DHID, T2, 1024, NNODES, 1024, DHID, nullptr, nullptr);

    // ---- on = adj @ T2[:, :512] + b2 + T2[:, 512:]  [650x512] ----
    nn_small_kernel<<<dim3(DNODE / 64, ceildiv(NNODES, 64)), 256>>>(
        adj, NNODES, T2, 1024, b2, T2 + 512, 1024, on, DNODE, NNODES, DNODE, NNODES);

    // ---- PP = blockdiag(on) @ Wp1^T  M=650,N=1200,K=1024  (PA rows / PO rows) ----
    mma2_kernel<3,1,0,160><<<dim3(ceildiv(P1D, 160), ceildiv(NNODES, 128)), 256, SM_S160>>>(
        on, DNODE, nullptr, 0, DNODE, wp1h, wp1l, 1024, PP, P1D, NNODES, P1D, 1024,
        nullptr, nullptr);

    // ---- Q = relu(PA_i + PO_j + bp1) @ Wp2^T + bp2  (fp16) ----
    mma2_kernel<1,0,0,160><<<dim3(EMBD / 160, ceildiv(NPAIRS, 128)), 256, SM_F160>>>(
        PP, P1D, PP + (size_t)NATTRS * P1D, P1D, 0, wp2h, nullptr, P1D,
        Q, EMBD, NPAIRS, EMBD, P1D, bp2, bp1);

    // ---- LN rows of Q -> fp16 P ----
    ln_half_kernel<<<NPAIRS, 256>>>(Q, gp, bpn, Ph);

    // ---- image MLP (split-bf16) ----
    zero_kernel<<<(BATCH * 1024 + 255) / 256, 256>>>(i2, BATCH * 1024);
    mma2_kernel<0,1,1,128><<<dim3(768 / 128, ceildiv(BATCH, 128)), 256, SM_S128>>>(
        img, FEATD, nullptr, 0, 0, wi1h, wi1l, FEATD, i1, 768, BATCH, 768, FEATD, bi1, nullptr);
    mma2_kernel<0,1,1,128><<<dim3(ceildiv(1000, 128), ceildiv(BATCH, 128)), 256, SM_S128>>>(
        i1, 768, nullptr, 0, 0, wi2h, wi2l, 768, i2, 1024, BATCH, 1000, 768, bi2, nullptr);
    mma2_kernel<0,1,0,160><<<dim3(EMBD / 160, ceildiv(BATCH, 128)), 256, SM_S160>>>(
        i2, 1024, nullptr, 0, 0, wi3h, wi3l, 1024, i3, EMBD, BATCH, EMBD, 1024, bi3, nullptr);
    ln_kernel<<<BATCH, 256>>>(i3, gi, bin_, EMBD);

    // ---- out = iLN @ P^T  (fp16)  [256 x 100000] ----
    mma2_kernel<0,0,0,160><<<dim3(NPAIRS / 160, ceildiv(BATCH, 128)), 256, SM_F160>>>(
        i3, EMBD, nullptr, 0, 0, Ph, nullptr, EMBD, out, NPAIRS, BATCH, NPAIRS, EMBD,
        nullptr, nullptr);
}